// round 1
// baseline (speedup 1.0000x reference)
#include <cuda_runtime.h>
#include <math.h>

#define BB 4
#define TT 1024
#define DD 512
#define EE 10
#define HH 2048
#define CEC 32
#define LIN 928
#define NTOK 4096
#define NPAIR 8192

#define TM 64
#define TN 64
#define TK 32

// Scratch (static device arrays — no allocation allowed)
__device__ float g_hid[(size_t)NPAIR * HH];   // 67 MB
__device__ int   g_count[EE];
__device__ int   g_entry[EE * NTOK];          // packed: token*2 + slot
__device__ float g_wt[EE * NTOK];

__global__ void zero_counts_kernel() {
    if (threadIdx.x < EE) g_count[threadIdx.x] = 0;
}

// ---------------------------------------------------------------------------
// Router: concat features -> 20 dot products -> softmax (gate1 out),
// noisy top-2 -> renormalized weights -> scatter to expert lists.
// One block per token, 256 threads.
// ---------------------------------------------------------------------------
__global__ void router_kernel(const float* __restrict__ x,
                              const float* __restrict__ dt,
                              const float* __restrict__ dd,
                              const float* __restrict__ dr,
                              const float* __restrict__ de,
                              const float* __restrict__ cemb,
                              const float* __restrict__ Wg,
                              const float* __restrict__ bg,
                              const float* __restrict__ Wn,
                              const float* __restrict__ bn,
                              const float* __restrict__ noise,
                              const int*   __restrict__ city,
                              float* __restrict__ gate1)
{
    __shared__ float h[LIN];
    __shared__ float lg[2 * EE];
    const int n = blockIdx.x;
    const int b = n / TT;
    const int tid = threadIdx.x;

    // Build concatenated feature vector h in smem
    for (int l = tid; l < DD; l += blockDim.x)  h[l]        = x[n * DD + l];
    if (tid < CEC)                              h[DD + tid] = cemb[city[b] * CEC + tid];
    for (int l = tid; l < 128; l += blockDim.x) h[544 + l]  = dt[n * 128 + l];
    for (int l = tid; l < 128; l += blockDim.x) h[672 + l]  = dd[n * 128 + l];
    for (int l = tid; l < 64;  l += blockDim.x) h[800 + l]  = dr[n * 64 + l];
    for (int l = tid; l < 64;  l += blockDim.x) h[864 + l]  = de[n * 64 + l];
    __syncthreads();

    const int warp = tid >> 5, lane = tid & 31;
    for (int j = warp; j < 2 * EE; j += 8) {
        const float* W = (j < EE) ? (Wg + j * LIN) : (Wn + (j - EE) * LIN);
        float s = 0.f;
        for (int l = lane; l < LIN; l += 32) s += h[l] * W[l];
        #pragma unroll
        for (int o = 16; o; o >>= 1) s += __shfl_down_sync(0xffffffffu, s, o);
        if (lane == 0) lg[j] = s + ((j < EE) ? bg[j] : bn[j - EE]);
    }
    __syncthreads();

    if (tid == 0) {
        float logits[EE], noisy[EE], ex[EE];
        float mx = -1e30f;
        for (int e = 0; e < EE; e++) { logits[e] = lg[e]; mx = fmaxf(mx, logits[e]); }
        float ssum = 0.f;
        for (int e = 0; e < EE; e++) { ex[e] = expf(logits[e] - mx); ssum += ex[e]; }
        const float rinv = 1.f / ssum;
        for (int e = 0; e < EE; e++) gate1[n * EE + e] = ex[e] * rinv;

        for (int e = 0; e < EE; e++) {
            const float z  = lg[EE + e];
            const float sp = fmaxf(z, 0.f) + log1pf(expf(-fabsf(z)));  // stable softplus
            noisy[e] = logits[e] + noise[n * EE + e] * sp;
        }
        // top-2, stable (lowest index wins ties) to match jax.lax.top_k
        int i0 = 0;
        for (int e = 1; e < EE; e++) if (noisy[e] > noisy[i0]) i0 = e;
        int i1 = (i0 == 0) ? 1 : 0;
        for (int e = 0; e < EE; e++) if (e != i0 && noisy[e] > noisy[i1]) i1 = e;

        const float m  = fmaxf(noisy[i0], noisy[i1]);
        const float s0 = expf(noisy[i0] - m), s1 = expf(noisy[i1] - m);
        const float inv = 1.f / (s0 + s1);

        int p0 = atomicAdd(&g_count[i0], 1);
        g_entry[i0 * NTOK + p0] = 2 * n;
        g_wt[i0 * NTOK + p0]    = s0 * inv;
        int p1 = atomicAdd(&g_count[i1], 1);
        g_entry[i1 * NTOK + p1] = 2 * n + 1;
        g_wt[i1 * NTOK + p1]    = s1 * inv;
    }
}

// ---------------------------------------------------------------------------
// Expert FFN layer 1: hid[pair] = gelu(x[tok] @ W1[e] + b1[e])
// Grid: (H/TN, NTOK/TM, E). Blocks past the token count exit immediately.
// ---------------------------------------------------------------------------
__global__ void expert_ffn1_kernel(const float* __restrict__ x,
                                   const float* __restrict__ W1,
                                   const float* __restrict__ b1)
{
    const int e  = blockIdx.z;
    const int m0 = blockIdx.y * TM;
    const int n0 = blockIdx.x * TN;
    const int L  = g_count[e];
    if (m0 >= L) return;

    __shared__ float As[TM][TK + 1];
    __shared__ float Bs[TK][TN];
    __shared__ int   toks[TM];

    const int tid = threadIdx.x;  // 256
    if (tid < TM) {
        int i = m0 + tid;
        toks[tid] = (i < L) ? g_entry[e * NTOK + i] : -1;
    }
    __syncthreads();

    const int tr = tid >> 4, tc = tid & 15;
    float acc[4][4] = {};
    const float* W1e = W1 + (size_t)e * DD * HH;

    for (int k0 = 0; k0 < DD; k0 += TK) {
        #pragma unroll
        for (int i = tid; i < TM * TK; i += 256) {
            int r = i / TK, c = i % TK;
            int ent = toks[r];
            As[r][c] = (ent >= 0) ? x[(size_t)(ent >> 1) * DD + k0 + c] : 0.f;
        }
        #pragma unroll
        for (int i = tid; i < TK * TN; i += 256) {
            int r = i / TN, c = i % TN;
            Bs[r][c] = W1e[(size_t)(k0 + r) * HH + n0 + c];
        }
        __syncthreads();
        #pragma unroll
        for (int kk = 0; kk < TK; kk++) {
            float a[4];
            #pragma unroll
            for (int u = 0; u < 4; u++) a[u] = As[tr * 4 + u][kk];
            const float4 b4 = *reinterpret_cast<const float4*>(&Bs[kk][tc * 4]);
            const float bb[4] = {b4.x, b4.y, b4.z, b4.w};
            #pragma unroll
            for (int u = 0; u < 4; u++)
                #pragma unroll
                for (int v = 0; v < 4; v++)
                    acc[u][v] += a[u] * bb[v];
        }
        __syncthreads();
    }

    #pragma unroll
    for (int u = 0; u < 4; u++) {
        const int r = tr * 4 + u;
        const int ent = toks[r];
        if (ent < 0) continue;
        #pragma unroll
        for (int v = 0; v < 4; v++) {
            const int col = n0 + tc * 4 + v;
            float val = acc[u][v] + b1[e * HH + col];
            val = 0.5f * val * (1.f + erff(val * 0.70710678118654752f));  // exact gelu
            g_hid[(size_t)ent * HH + col] = val;
        }
    }
}

// ---------------------------------------------------------------------------
// Expert FFN layer 2: out[tok] += w * (hid[pair] @ W2[e] + b2[e])
// Grid: (D/TN, NTOK/TM, E).
// ---------------------------------------------------------------------------
__global__ void expert_ffn2_kernel(const float* __restrict__ W2,
                                   const float* __restrict__ b2,
                                   float* __restrict__ out)
{
    const int e  = blockIdx.z;
    const int m0 = blockIdx.y * TM;
    const int n0 = blockIdx.x * TN;
    const int L  = g_count[e];
    if (m0 >= L) return;

    __shared__ float As[TM][TK + 1];
    __shared__ float Bs[TK][TN];
    __shared__ int   toks[TM];
    __shared__ float wts[TM];

    const int tid = threadIdx.x;
    if (tid < TM) {
        int i = m0 + tid;
        toks[tid] = (i < L) ? g_entry[e * NTOK + i] : -1;
        wts[tid]  = (i < L) ? g_wt[e * NTOK + i]    : 0.f;
    }
    __syncthreads();

    const int tr = tid >> 4, tc = tid & 15;
    float acc[4][4] = {};
    const float* W2e = W2 + (size_t)e * HH * DD;

    for (int k0 = 0; k0 < HH; k0 += TK) {
        #pragma unroll
        for (int i = tid; i < TM * TK; i += 256) {
            int r = i / TK, c = i % TK;
            int ent = toks[r];
            As[r][c] = (ent >= 0) ? g_hid[(size_t)ent * HH + k0 + c] : 0.f;
        }
        #pragma unroll
        for (int i = tid; i < TK * TN; i += 256) {
            int r = i / TN, c = i % TN;
            Bs[r][c] = W2e[(size_t)(k0 + r) * DD + n0 + c];
        }
        __syncthreads();
        #pragma unroll
        for (int kk = 0; kk < TK; kk++) {
            float a[4];
            #pragma unroll
            for (int u = 0; u < 4; u++) a[u] = As[tr * 4 + u][kk];
            const float4 b4 = *reinterpret_cast<const float4*>(&Bs[kk][tc * 4]);
            const float bb[4] = {b4.x, b4.y, b4.z, b4.w};
            #pragma unroll
            for (int u = 0; u < 4; u++)
                #pragma unroll
                for (int v = 0; v < 4; v++)
                    acc[u][v] += a[u] * bb[v];
        }
        __syncthreads();
    }

    #pragma unroll
    for (int u = 0; u < 4; u++) {
        const int r = tr * 4 + u;
        const int ent = toks[r];
        if (ent < 0) continue;
        const int tok = ent >> 1;
        const float w = wts[r];
        #pragma unroll
        for (int v = 0; v < 4; v++) {
            const int col = n0 + tc * 4 + v;
            atomicAdd(&out[(size_t)tok * DD + col],
                      w * (acc[u][v] + b2[e * DD + col]));
        }
    }
}

// ---------------------------------------------------------------------------
extern "C" void kernel_launch(void* const* d_in, const int* in_sizes, int n_in,
                              void* d_out, int out_size)
{
    const float* x    = (const float*)d_in[0];
    const float* dt   = (const float*)d_in[1];
    const float* dd   = (const float*)d_in[2];
    const float* dr   = (const float*)d_in[3];
    const float* de   = (const float*)d_in[4];
    const float* cemb = (const float*)d_in[5];
    const float* Wg   = (const float*)d_in[6];
    const float* bg   = (const float*)d_in[7];
    const float* Wn   = (const float*)d_in[8];
    const float* bn   = (const float*)d_in[9];
    const float* W1   = (const float*)d_in[10];
    const float* b1   = (const float*)d_in[11];
    const float* W2   = (const float*)d_in[12];
    const float* b2   = (const float*)d_in[13];
    const float* noise= (const float*)d_in[14];
    const int*   city = (const int*)d_in[15];

    float* out   = (float*)d_out;                       // (4096, 512)
    float* gate1 = (float*)d_out + (size_t)NTOK * DD;   // (4096, 10)

    // zero the accumulation region (gate1 is fully overwritten by router)
    cudaMemsetAsync(d_out, 0, (size_t)NTOK * DD * sizeof(float));
    zero_counts_kernel<<<1, 32>>>();

    router_kernel<<<NTOK, 256>>>(x, dt, dd, dr, de, cemb, Wg, bg, Wn, bn,
                                 noise, city, gate1);

    dim3 grid1(HH / TN, NTOK / TM, EE);   // (32, 64, 10)
    expert_ffn1_kernel<<<grid1, 256>>>(x, W1, b1);

    dim3 grid2(DD / TN, NTOK / TM, EE);   // (8, 64, 10)
    expert_ffn2_kernel<<<grid2, 256>>>(W2, b2, out);
}

// round 2
// speedup vs baseline: 2.5413x; 2.5413x over previous
#include <cuda_runtime.h>
#include <math.h>

#define BB 4
#define TT 1024
#define DD 512
#define EE 10
#define HH 2048
#define CEC 32
#define LIN 928
#define NTOK 4096
#define NPAIR 8192

#define BM 128
#define BN 128
#define BKT 16

// Scratch (static device arrays — no allocation allowed)
__device__ float g_hid[(size_t)NPAIR * HH];   // 67 MB
__device__ int   g_count[EE];
__device__ int   g_entry[EE * NTOK];          // packed: token*2 + slot
__device__ float g_wt[EE * NTOK];

__global__ void zero_counts_kernel() {
    if (threadIdx.x < EE) g_count[threadIdx.x] = 0;
}

// ---------------------------------------------------------------------------
// Router (unchanged from R1): concat -> 20 dots -> softmax gate1, noisy top-2,
// scatter to per-expert lists.
// ---------------------------------------------------------------------------
__global__ void router_kernel(const float* __restrict__ x,
                              const float* __restrict__ dt,
                              const float* __restrict__ dd,
                              const float* __restrict__ dr,
                              const float* __restrict__ de,
                              const float* __restrict__ cemb,
                              const float* __restrict__ Wg,
                              const float* __restrict__ bg,
                              const float* __restrict__ Wn,
                              const float* __restrict__ bn,
                              const float* __restrict__ noise,
                              const int*   __restrict__ city,
                              float* __restrict__ gate1)
{
    __shared__ float h[LIN];
    __shared__ float lg[2 * EE];
    const int n = blockIdx.x;
    const int b = n / TT;
    const int tid = threadIdx.x;

    for (int l = tid; l < DD; l += blockDim.x)  h[l]        = x[n * DD + l];
    if (tid < CEC)                              h[DD + tid] = cemb[city[b] * CEC + tid];
    for (int l = tid; l < 128; l += blockDim.x) h[544 + l]  = dt[n * 128 + l];
    for (int l = tid; l < 128; l += blockDim.x) h[672 + l]  = dd[n * 128 + l];
    for (int l = tid; l < 64;  l += blockDim.x) h[800 + l]  = dr[n * 64 + l];
    for (int l = tid; l < 64;  l += blockDim.x) h[864 + l]  = de[n * 64 + l];
    __syncthreads();

    const int warp = tid >> 5, lane = tid & 31;
    for (int j = warp; j < 2 * EE; j += 8) {
        const float* W = (j < EE) ? (Wg + j * LIN) : (Wn + (j - EE) * LIN);
        float s = 0.f;
        for (int l = lane; l < LIN; l += 32) s += h[l] * W[l];
        #pragma unroll
        for (int o = 16; o; o >>= 1) s += __shfl_down_sync(0xffffffffu, s, o);
        if (lane == 0) lg[j] = s + ((j < EE) ? bg[j] : bn[j - EE]);
    }
    __syncthreads();

    if (tid == 0) {
        float logits[EE], noisy[EE], ex[EE];
        float mx = -1e30f;
        for (int e = 0; e < EE; e++) { logits[e] = lg[e]; mx = fmaxf(mx, logits[e]); }
        float ssum = 0.f;
        for (int e = 0; e < EE; e++) { ex[e] = expf(logits[e] - mx); ssum += ex[e]; }
        const float rinv = 1.f / ssum;
        for (int e = 0; e < EE; e++) gate1[n * EE + e] = ex[e] * rinv;

        for (int e = 0; e < EE; e++) {
            const float z  = lg[EE + e];
            const float sp = fmaxf(z, 0.f) + log1pf(expf(-fabsf(z)));
            noisy[e] = logits[e] + noise[n * EE + e] * sp;
        }
        int i0 = 0;
        for (int e = 1; e < EE; e++) if (noisy[e] > noisy[i0]) i0 = e;
        int i1 = (i0 == 0) ? 1 : 0;
        for (int e = 0; e < EE; e++) if (e != i0 && noisy[e] > noisy[i1]) i1 = e;

        const float m  = fmaxf(noisy[i0], noisy[i1]);
        const float s0 = expf(noisy[i0] - m), s1 = expf(noisy[i1] - m);
        const float inv = 1.f / (s0 + s1);

        int p0 = atomicAdd(&g_count[i0], 1);
        g_entry[i0 * NTOK + p0] = 2 * n;
        g_wt[i0 * NTOK + p0]    = s0 * inv;
        int p1 = atomicAdd(&g_count[i1], 1);
        g_entry[i1 * NTOK + p1] = 2 * n + 1;
        g_wt[i1 * NTOK + p1]    = s1 * inv;
    }
}

// ---------------------------------------------------------------------------
// TF32 helpers
// ---------------------------------------------------------------------------
__device__ __forceinline__ unsigned f2tf32(float v) {
    unsigned r;
    asm("cvt.rna.tf32.f32 %0, %1;" : "=r"(r) : "f"(v));
    return r;
}

#define MMA_TF32(d, a0, a1, a2, a3, b0, b1)                                   \
    asm volatile(                                                             \
        "mma.sync.aligned.m16n8k8.row.col.f32.tf32.tf32.f32 "                 \
        "{%0,%1,%2,%3}, {%4,%5,%6,%7}, {%8,%9}, {%0,%1,%2,%3};"               \
        : "+f"((d)[0]), "+f"((d)[1]), "+f"((d)[2]), "+f"((d)[3])              \
        : "r"(a0), "r"(a1), "r"(a2), "r"(a3), "r"(b0), "r"(b1))

// ---------------------------------------------------------------------------
// Gathered expert GEMM on tensor cores (3xTF32, fp32 accuracy).
//   IS_FFN2 == false: hid[pair] = gelu(x[tok] @ W1[e] + b1[e])   (K=512, N=2048)
//   IS_FFN2 == true : out[tok] += w * (hid[pair] @ W2[e] + b2[e]) (K=2048, N=512)
// Block tile 128x128, BK=16, 256 threads (8 warps, 4x2), warp tile 32x64.
// Smem XOR-swizzled k-major tiles: elem (k, c) at [k*128 + (c ^ ((k&3)<<3))].
// ---------------------------------------------------------------------------
template<int KTOT, int LDW, bool IS_FFN2>
__global__ __launch_bounds__(256, 1)
void moe_mma_kernel(const float* __restrict__ Asrc,
                    const float* __restrict__ W,
                    const float* __restrict__ bias,
                    float* __restrict__ outp)
{
    const int e  = blockIdx.z;
    const int m0 = blockIdx.y * BM;
    const int n0 = blockIdx.x * BN;
    const int L  = g_count[e];
    if (m0 >= L) return;

    __shared__ float As[2][BKT * BM];
    __shared__ float Bs[2][BKT * BN];
    __shared__ int   toks[BM];
    __shared__ float wts[BM];

    const int tid = threadIdx.x;
    if (tid < BM) {
        int i = m0 + tid;
        int ent = (i < L) ? g_entry[e * NTOK + i] : -1;
        toks[tid] = ent;
        wts[tid]  = (IS_FFN2 && i < L) ? g_wt[e * NTOK + i] : 0.f;
    }
    __syncthreads();

    const float* Asrc_eff = IS_FFN2 ? (const float*)g_hid : Asrc;
    const float* Wp = W + (size_t)e * KTOT * LDW + n0;

    // ---- fill-role indices ----
    const int ar  = tid & 127;      // A tile row
    const int ahf = tid >> 7;       // A k-half (0/1)
    const float* aptr = nullptr;
    {
        int ent = toks[ar];
        if (ent >= 0) {
            int rowidx = IS_FFN2 ? ent : (ent >> 1);
            aptr = Asrc_eff + (size_t)rowidx * KTOT + ahf * 8;
        }
    }
    const int bk0 = tid >> 5,          bj0 = (tid & 31) * 4;
    const int bk1 = (tid + 256) >> 5,  bj1 = (tid & 31) * 4;

    float4 av0, av1, bv0, bv1;

#define LDSTAGE(K0) do {                                                      \
        if (aptr) {                                                           \
            av0 = *(const float4*)(aptr + (K0));                              \
            av1 = *(const float4*)(aptr + (K0) + 4);                          \
        } else { av0 = make_float4(0,0,0,0); av1 = av0; }                     \
        bv0 = *(const float4*)(Wp + (size_t)((K0) + bk0) * LDW + bj0);        \
        bv1 = *(const float4*)(Wp + (size_t)((K0) + bk1) * LDW + bj1);        \
    } while (0)

#define STSTAGE(BUF) do {                                                     \
        float va[8] = {av0.x, av0.y, av0.z, av0.w, av1.x, av1.y, av1.z, av1.w};\
        _Pragma("unroll")                                                     \
        for (int j = 0; j < 8; j++) {                                         \
            int k = ahf * 8 + j;                                              \
            As[BUF][k * BM + (ar ^ ((k & 3) << 3))] = va[j];                  \
        }                                                                     \
        *(float4*)&Bs[BUF][bk0 * BN + (bj0 ^ ((bk0 & 3) << 3))] = bv0;        \
        *(float4*)&Bs[BUF][bk1 * BN + (bj1 ^ ((bk1 & 3) << 3))] = bv1;        \
    } while (0)

    // ---- compute-role indices ----
    const int warp = tid >> 5;
    const int wm   = warp >> 1;     // 0..3
    const int wn   = warp & 1;      // 0..1
    const int lane = tid & 31;
    const int g    = lane >> 2;
    const int kq   = lane & 3;
    const int mb   = wm * 32;
    const int nb   = wn * 64;
    const int swz  = kq << 3;

    float acc[2][8][4];
    #pragma unroll
    for (int mm = 0; mm < 2; mm++)
        #pragma unroll
        for (int nn = 0; nn < 8; nn++)
            #pragma unroll
            for (int i = 0; i < 4; i++) acc[mm][nn][i] = 0.f;

    constexpr int NT = KTOT / BKT;

    LDSTAGE(0);
    STSTAGE(0);
    __syncthreads();

    for (int t = 0; t < NT; t++) {
        const int buf = t & 1;
        if (t + 1 < NT) LDSTAGE((t + 1) * BKT);

        #pragma unroll
        for (int ks = 0; ks < 2; ks++) {
            const int kb = ks * 8;
            unsigned ahx[2][4], alx[2][4];
            #pragma unroll
            for (int mm = 0; mm < 2; mm++) {
                const int r  = mb + mm * 16 + g;
                const int c0 = r ^ swz;
                const int c1 = (r + 8) ^ swz;
                float r0 = As[buf][(kb + kq)     * BM + c0];
                float r1 = As[buf][(kb + kq)     * BM + c1];
                float r2 = As[buf][(kb + kq + 4) * BM + c0];
                float r3 = As[buf][(kb + kq + 4) * BM + c1];
                ahx[mm][0] = f2tf32(r0); alx[mm][0] = f2tf32(r0 - __uint_as_float(ahx[mm][0]));
                ahx[mm][1] = f2tf32(r1); alx[mm][1] = f2tf32(r1 - __uint_as_float(ahx[mm][1]));
                ahx[mm][2] = f2tf32(r2); alx[mm][2] = f2tf32(r2 - __uint_as_float(ahx[mm][2]));
                ahx[mm][3] = f2tf32(r3); alx[mm][3] = f2tf32(r3 - __uint_as_float(ahx[mm][3]));
            }
            #pragma unroll
            for (int nn = 0; nn < 8; nn++) {
                const int n  = nb + nn * 8 + g;
                const int cs = n ^ swz;
                float b0 = Bs[buf][(kb + kq)     * BN + cs];
                float b1 = Bs[buf][(kb + kq + 4) * BN + cs];
                unsigned bh0 = f2tf32(b0), bl0 = f2tf32(b0 - __uint_as_float(bh0));
                unsigned bh1 = f2tf32(b1), bl1 = f2tf32(b1 - __uint_as_float(bh1));
                #pragma unroll
                for (int mm = 0; mm < 2; mm++) {
                    MMA_TF32(acc[mm][nn], ahx[mm][0], ahx[mm][1], ahx[mm][2], ahx[mm][3], bh0, bh1);
                    MMA_TF32(acc[mm][nn], ahx[mm][0], ahx[mm][1], ahx[mm][2], ahx[mm][3], bl0, bl1);
                    MMA_TF32(acc[mm][nn], alx[mm][0], alx[mm][1], alx[mm][2], alx[mm][3], bh0, bh1);
                }
            }
        }

        if (t + 1 < NT) STSTAGE((t + 1) & 1);
        __syncthreads();
    }

    // ---- epilogue ----
    const float* be = bias + e * LDW;
    #pragma unroll
    for (int mm = 0; mm < 2; mm++) {
        const int lr0  = mb + mm * 16 + g;
        const int ent0 = toks[lr0];
        const int ent1 = toks[lr0 + 8];
        #pragma unroll
        for (int nn = 0; nn < 8; nn++) {
            const int c = n0 + nb + nn * 8 + 2 * kq;
            const float bb0 = be[c], bb1 = be[c + 1];
            if (!IS_FFN2) {
                if (ent0 >= 0) {
                    float v0 = acc[mm][nn][0] + bb0;
                    float v1 = acc[mm][nn][1] + bb1;
                    v0 = 0.5f * v0 * (1.f + erff(v0 * 0.70710678118654752f));
                    v1 = 0.5f * v1 * (1.f + erff(v1 * 0.70710678118654752f));
                    *(float2*)&g_hid[(size_t)ent0 * HH + c] = make_float2(v0, v1);
                }
                if (ent1 >= 0) {
                    float v0 = acc[mm][nn][2] + bb0;
                    float v1 = acc[mm][nn][3] + bb1;
                    v0 = 0.5f * v0 * (1.f + erff(v0 * 0.70710678118654752f));
                    v1 = 0.5f * v1 * (1.f + erff(v1 * 0.70710678118654752f));
                    *(float2*)&g_hid[(size_t)ent1 * HH + c] = make_float2(v0, v1);
                }
            } else {
                if (ent0 >= 0) {
                    const float w = wts[lr0];
                    float* o = outp + (size_t)(ent0 >> 1) * DD + c;
                    atomicAdd(o,     w * (acc[mm][nn][0] + bb0));
                    atomicAdd(o + 1, w * (acc[mm][nn][1] + bb1));
                }
                if (ent1 >= 0) {
                    const float w = wts[lr0 + 8];
                    float* o = outp + (size_t)(ent1 >> 1) * DD + c;
                    atomicAdd(o,     w * (acc[mm][nn][2] + bb0));
                    atomicAdd(o + 1, w * (acc[mm][nn][3] + bb1));
                }
            }
        }
    }
#undef LDSTAGE
#undef STSTAGE
}

// ---------------------------------------------------------------------------
extern "C" void kernel_launch(void* const* d_in, const int* in_sizes, int n_in,
                              void* d_out, int out_size)
{
    const float* x    = (const float*)d_in[0];
    const float* dt   = (const float*)d_in[1];
    const float* dd   = (const float*)d_in[2];
    const float* dr   = (const float*)d_in[3];
    const float* de   = (const float*)d_in[4];
    const float* cemb = (const float*)d_in[5];
    const float* Wg   = (const float*)d_in[6];
    const float* bg   = (const float*)d_in[7];
    const float* Wn   = (const float*)d_in[8];
    const float* bn   = (const float*)d_in[9];
    const float* W1   = (const float*)d_in[10];
    const float* b1   = (const float*)d_in[11];
    const float* W2   = (const float*)d_in[12];
    const float* b2   = (const float*)d_in[13];
    const float* noise= (const float*)d_in[14];
    const int*   city = (const int*)d_in[15];

    float* out   = (float*)d_out;                       // (4096, 512)
    float* gate1 = (float*)d_out + (size_t)NTOK * DD;   // (4096, 10)

    cudaMemsetAsync(d_out, 0, (size_t)NTOK * DD * sizeof(float));
    zero_counts_kernel<<<1, 32>>>();

    router_kernel<<<NTOK, 256>>>(x, dt, dd, dr, de, cemb, Wg, bg, Wn, bn,
                                 noise, city, gate1);

    dim3 grid1(HH / BN, NTOK / BM, EE);   // (16, 32, 10)
    moe_mma_kernel<DD, HH, false><<<grid1, 256>>>(x, W1, b1, nullptr);

    dim3 grid2(DD / BN, NTOK / BM, EE);   // (4, 32, 10)
    moe_mma_kernel<HH, DD, true><<<grid2, 256>>>(nullptr, W2, b2, out);
}

// round 6
// speedup vs baseline: 2.8268x; 1.1124x over previous
#include <cuda_runtime.h>
#include <cuda_bf16.h>
#include <math.h>
#include <stdint.h>

#define TT 1024
#define DD 512
#define EE 10
#define HH 2048
#define CEC 32
#define LIN 928
#define NTOK 4096
#define NPAIR 8192

#define BM 128
#define BN 128
#define BK 32           // bf16 k per stage

// A tile: 128 rows x 32 bf16, 80B pitch (conflict-free ldmatrix) = 10240B
// B tile: 32 k-rows x 128 bf16, 256B pitch, chunk-XOR swizzle = 8192B
#define A_TILE 10240
#define B_TILE 8192
#define OFF_AH 0
#define OFF_AL A_TILE
#define OFF_BH (2 * A_TILE)
#define OFF_BL (2 * A_TILE + B_TILE)
#define STAGE  (2 * A_TILE + 2 * B_TILE)   // 36864
#define SMEM_DYN (2 * STAGE)               // 73728

// Scratch (static device arrays — no allocation allowed)
__device__ __nv_bfloat16 g_hid_h[(size_t)NPAIR * HH];   // 32 MB
__device__ __nv_bfloat16 g_hid_l[(size_t)NPAIR * HH];   // 32 MB
__device__ int   g_count[EE];
__device__ int   g_entry[EE * NTOK];          // packed: token*2 + slot
__device__ float g_wt[EE * NTOK];

__global__ void zero_counts_kernel() {
    if (threadIdx.x < EE) g_count[threadIdx.x] = 0;
}

// ---------------------------------------------------------------------------
// helpers
// ---------------------------------------------------------------------------
__device__ __forceinline__ uint32_t sm_u32(const void* p) {
    return (uint32_t)__cvta_generic_to_shared(p);
}
__device__ __forceinline__ void bsplit(float v, uint32_t& h, uint32_t& l) {
    __nv_bfloat16 bh = __float2bfloat16_rn(v);
    h = (uint32_t)__bfloat16_as_ushort(bh);
    l = (uint32_t)__bfloat16_as_ushort(__float2bfloat16_rn(v - __bfloat162float(bh)));
}

#define MMA_BF16(d, a0, a1, a2, a3, b0, b1)                                   \
    asm volatile(                                                             \
        "mma.sync.aligned.m16n8k16.row.col.f32.bf16.bf16.f32 "                \
        "{%0,%1,%2,%3}, {%4,%5,%6,%7}, {%8,%9}, {%0,%1,%2,%3};"               \
        : "+f"((d)[0]), "+f"((d)[1]), "+f"((d)[2]), "+f"((d)[3])              \
        : "r"(a0), "r"(a1), "r"(a2), "r"(a3), "r"(b0), "r"(b1))

#define LDSM_X4(r0, r1, r2, r3, addr)                                         \
    asm volatile("ldmatrix.sync.aligned.m8n8.x4.shared.b16 {%0,%1,%2,%3}, [%4];" \
        : "=r"(r0), "=r"(r1), "=r"(r2), "=r"(r3) : "r"(addr))

#define LDSM_X4T(r0, r1, r2, r3, addr)                                        \
    asm volatile("ldmatrix.sync.aligned.m8n8.x4.trans.shared.b16 {%0,%1,%2,%3}, [%4];" \
        : "=r"(r0), "=r"(r1), "=r"(r2), "=r"(r3) : "r"(addr))

// ---------------------------------------------------------------------------
// Router: 32 tokens per block, weights staged in smem.
// ---------------------------------------------------------------------------
#define RTOK 32
#define RCH 116   // 928 / 8 chunks

__global__ __launch_bounds__(256)
void router_kernel(const float* __restrict__ x,
                   const float* __restrict__ dt,
                   const float* __restrict__ dd,
                   const float* __restrict__ dr,
                   const float* __restrict__ de,
                   const float* __restrict__ cemb,
                   const float* __restrict__ Wg,
                   const float* __restrict__ bg,
                   const float* __restrict__ Wn,
                   const float* __restrict__ bn,
                   const float* __restrict__ noise,
                   const int*   __restrict__ city,
                   float* __restrict__ gate1)
{
    __shared__ float Wsh[2 * EE][RCH];
    __shared__ float hsh[RTOK][RCH];
    __shared__ float lg[RTOK][2 * EE];

    const int tid = threadIdx.x;          // 256
    const int tb = blockIdx.x * RTOK;
    const int t = tid >> 3;               // token slot 0..31
    const int s = tid & 7;                // 0..7

    float acc0 = 0.f, acc1 = 0.f, acc2 = 0.f;

    for (int c = 0; c < 8; c++) {
        const int k0 = c * RCH;
        for (int i = tid; i < 2 * EE * RCH; i += 256) {
            int j = i / RCH, k = i % RCH;
            Wsh[j][k] = (j < EE) ? Wg[j * LIN + k0 + k] : Wn[(j - EE) * LIN + k0 + k];
        }
        for (int i = tid; i < RTOK * RCH; i += 256) {
            int tt = i / RCH, kk = i % RCH;
            int k = k0 + kk;
            int n = tb + tt;
            float v;
            if (k < DD)        v = x[n * DD + k];
            else if (k < 544)  v = cemb[city[n / TT] * CEC + (k - DD)];
            else if (k < 672)  v = dt[n * 128 + (k - 544)];
            else if (k < 800)  v = dd[n * 128 + (k - 672)];
            else if (k < 864)  v = dr[n * 64 + (k - 800)];
            else               v = de[n * 64 + (k - 864)];
            hsh[tt][kk] = v;
        }
        __syncthreads();
        for (int k = 0; k < RCH; k++) {
            float a = hsh[t][k];
            acc0 += a * Wsh[s][k];
            acc1 += a * Wsh[s + 8][k];
            if (s < 4) acc2 += a * Wsh[s + 16][k];
        }
        __syncthreads();
    }
    lg[t][s] = acc0;
    lg[t][s + 8] = acc1;
    if (s < 4) lg[t][s + 16] = acc2;
    __syncthreads();

    if (s == 0) {
        const int n = tb + t;
        float logits[EE], noisy[EE], ex[EE];
        float mx = -1e30f;
        for (int e = 0; e < EE; e++) { logits[e] = lg[t][e] + bg[e]; mx = fmaxf(mx, logits[e]); }
        float ssum = 0.f;
        for (int e = 0; e < EE; e++) { ex[e] = expf(logits[e] - mx); ssum += ex[e]; }
        const float rinv = 1.f / ssum;
        for (int e = 0; e < EE; e++) gate1[n * EE + e] = ex[e] * rinv;

        for (int e = 0; e < EE; e++) {
            const float z  = lg[t][EE + e] + bn[e];
            const float sp = fmaxf(z, 0.f) + log1pf(expf(-fabsf(z)));  // stable softplus
            noisy[e] = logits[e] + noise[n * EE + e] * sp;
        }
        int i0 = 0;
        for (int e = 1; e < EE; e++) if (noisy[e] > noisy[i0]) i0 = e;
        int i1 = (i0 == 0) ? 1 : 0;
        for (int e = 0; e < EE; e++) if (e != i0 && noisy[e] > noisy[i1]) i1 = e;

        const float m  = fmaxf(noisy[i0], noisy[i1]);
        const float s0 = expf(noisy[i0] - m), s1 = expf(noisy[i1] - m);
        const float inv = 1.f / (s0 + s1);

        int p0 = atomicAdd(&g_count[i0], 1);
        g_entry[i0 * NTOK + p0] = 2 * n;
        g_wt[i0 * NTOK + p0]    = s0 * inv;
        int p1 = atomicAdd(&g_count[i1], 1);
        g_entry[i1 * NTOK + p1] = 2 * n + 1;
        g_wt[i1 * NTOK + p1]    = s1 * inv;
    }
}

// ---------------------------------------------------------------------------
// Gathered expert GEMM: mma.sync m16n8k16 bf16, 3xBF16 split, fp32 accum.
//   IS_FFN2 == false: hid(hi,lo)[pair] = split(gelu(x[tok] @ W1[e] + b1[e]))
//   IS_FFN2 == true : out[tok] += w * (hid[pair] @ W2[e] + b2[e])
// Block 128x128, BK=32 (2 k-steps of 16), 8 warps 4x2, warp tile 32x64.
// A smem [m][k] 80B pitch; B smem [k][n] 256B pitch, chunk c ^= (k&7).
// ---------------------------------------------------------------------------
template<int KTOT, int LDW, bool IS_FFN2>
__global__ __launch_bounds__(256, 1)
void moe_mma_kernel(const float* __restrict__ Asrc,
                    const float* __restrict__ W,
                    const float* __restrict__ bias,
                    float* __restrict__ outp)
{
    constexpr int NT = KTOT / BK;
    const int e  = blockIdx.z;
    const int m0 = blockIdx.y * BM;
    const int n0 = blockIdx.x * BN;
    const int L  = g_count[e];
    if (m0 >= L) return;

    extern __shared__ char smem[];
    __shared__ int   toks[BM];
    __shared__ float wts[BM];

    const int tid  = threadIdx.x;
    const int wid  = tid >> 5;
    const int lane = tid & 31;

    if (tid < BM) {
        int i = m0 + tid;
        toks[tid] = (i < L) ? g_entry[e * NTOK + i] : -1;
        wts[tid]  = (IS_FFN2 && i < L) ? g_wt[e * NTOK + i] : 0.f;
    }
    __syncthreads();

    const float* Wp = W + (size_t)e * KTOT * LDW + n0;

    // ---- fills ----
    auto fill_stage = [&](int buf, int k0) {
        char* st = smem + buf * STAGE;
        // A: 128 rows x 4 chunks of 8; two passes
        #pragma unroll
        for (int p = 0; p < 2; p++) {
            const int idx = p * 256 + tid;
            const int r = idx >> 2, c = idx & 3;
            const int ent = toks[r];
            uint4 hp = make_uint4(0, 0, 0, 0), lp = hp;
            if (ent >= 0) {
                if (IS_FFN2) {
                    const size_t o = ((size_t)ent * KTOT + k0 + c * 8) * 2;
                    hp = *(const uint4*)((const char*)g_hid_h + o);
                    lp = *(const uint4*)((const char*)g_hid_l + o);
                } else {
                    const float* ar = Asrc + (size_t)(ent >> 1) * KTOT + k0 + c * 8;
                    float4 v0 = *(const float4*)ar;
                    float4 v1 = *(const float4*)(ar + 4);
                    uint32_t h[8], l[8];
                    bsplit(v0.x, h[0], l[0]); bsplit(v0.y, h[1], l[1]);
                    bsplit(v0.z, h[2], l[2]); bsplit(v0.w, h[3], l[3]);
                    bsplit(v1.x, h[4], l[4]); bsplit(v1.y, h[5], l[5]);
                    bsplit(v1.z, h[6], l[6]); bsplit(v1.w, h[7], l[7]);
                    hp = make_uint4(h[0] | (h[1] << 16), h[2] | (h[3] << 16),
                                    h[4] | (h[5] << 16), h[6] | (h[7] << 16));
                    lp = make_uint4(l[0] | (l[1] << 16), l[2] | (l[3] << 16),
                                    l[4] | (l[5] << 16), l[6] | (l[7] << 16));
                }
            }
            *(uint4*)(st + OFF_AH + r * 80 + c * 16) = hp;
            *(uint4*)(st + OFF_AL + r * 80 + c * 16) = lp;
        }
        // B: 32 k-rows x 16 chunks of 8; two passes
        #pragma unroll
        for (int p = 0; p < 2; p++) {
            const int idx = p * 256 + tid;
            const int k = idx >> 4, c = idx & 15;
            const float* wr = Wp + (size_t)(k0 + k) * LDW + c * 8;
            float4 v0 = *(const float4*)wr;
            float4 v1 = *(const float4*)(wr + 4);
            uint32_t h[8], l[8];
            bsplit(v0.x, h[0], l[0]); bsplit(v0.y, h[1], l[1]);
            bsplit(v0.z, h[2], l[2]); bsplit(v0.w, h[3], l[3]);
            bsplit(v1.x, h[4], l[4]); bsplit(v1.y, h[5], l[5]);
            bsplit(v1.z, h[6], l[6]); bsplit(v1.w, h[7], l[7]);
            uint4 hp = make_uint4(h[0] | (h[1] << 16), h[2] | (h[3] << 16),
                                  h[4] | (h[5] << 16), h[6] | (h[7] << 16));
            uint4 lp = make_uint4(l[0] | (l[1] << 16), l[2] | (l[3] << 16),
                                  l[4] | (l[5] << 16), l[6] | (l[7] << 16));
            const int off = k * 256 + ((c ^ (k & 7)) * 16);
            *(uint4*)(st + OFF_BH + off) = hp;
            *(uint4*)(st + OFF_BL + off) = lp;
        }
    };

    // ---- accumulators ----
    const int wm = wid >> 1, wn = wid & 1;
    float acc[2][8][4];
    #pragma unroll
    for (int mt = 0; mt < 2; mt++)
        #pragma unroll
        for (int nn = 0; nn < 8; nn++)
            #pragma unroll
            for (int i = 0; i < 4; i++) acc[mt][nn][i] = 0.f;

    auto compute_stage = [&](int buf) {
        char* st = smem + buf * STAGE;
        const uint32_t ah = sm_u32(st + OFF_AH);
        const uint32_t al = sm_u32(st + OFF_AL);
        const uint32_t bh = sm_u32(st + OFF_BH);
        const uint32_t bl = sm_u32(st + OFF_BL);
        #pragma unroll
        for (int ks = 0; ks < 2; ks++) {
            // A frags: rows lane&15, k-half lane>>4
            uint32_t a_h[2][4], a_l[2][4];
            #pragma unroll
            for (int mt = 0; mt < 2; mt++) {
                const uint32_t ao = (wm * 32 + mt * 16 + (lane & 15)) * 80
                                  + ks * 32 + (lane >> 4) * 16;
                LDSM_X4(a_h[mt][0], a_h[mt][1], a_h[mt][2], a_h[mt][3], ah + ao);
                LDSM_X4(a_l[mt][0], a_l[mt][1], a_l[mt][2], a_l[mt][3], al + ao);
            }
            // B frags: k-rows ks*16 + lane&15, n chunk + (lane>>4)
            uint32_t b_h[4][4], b_l[4][4];
            #pragma unroll
            for (int bt = 0; bt < 4; bt++) {
                const int k = ks * 16 + (lane & 15);
                const int c = ((wn * 64 + bt * 16) >> 3) + (lane >> 4);
                const uint32_t bo = k * 256 + ((c ^ (lane & 7)) * 16);
                LDSM_X4T(b_h[bt][0], b_h[bt][1], b_h[bt][2], b_h[bt][3], bh + bo);
                LDSM_X4T(b_l[bt][0], b_l[bt][1], b_l[bt][2], b_l[bt][3], bl + bo);
            }
            #pragma unroll
            for (int mt = 0; mt < 2; mt++) {
                #pragma unroll
                for (int bt = 0; bt < 4; bt++) {
                    float* d0 = acc[mt][2 * bt];
                    float* d1 = acc[mt][2 * bt + 1];
                    MMA_BF16(d0, a_h[mt][0], a_h[mt][1], a_h[mt][2], a_h[mt][3],
                             b_h[bt][0], b_h[bt][1]);
                    MMA_BF16(d0, a_h[mt][0], a_h[mt][1], a_h[mt][2], a_h[mt][3],
                             b_l[bt][0], b_l[bt][1]);
                    MMA_BF16(d0, a_l[mt][0], a_l[mt][1], a_l[mt][2], a_l[mt][3],
                             b_h[bt][0], b_h[bt][1]);
                    MMA_BF16(d1, a_h[mt][0], a_h[mt][1], a_h[mt][2], a_h[mt][3],
                             b_h[bt][2], b_h[bt][3]);
                    MMA_BF16(d1, a_h[mt][0], a_h[mt][1], a_h[mt][2], a_h[mt][3],
                             b_l[bt][2], b_l[bt][3]);
                    MMA_BF16(d1, a_l[mt][0], a_l[mt][1], a_l[mt][2], a_l[mt][3],
                             b_h[bt][2], b_h[bt][3]);
                }
            }
        }
    };

    // ---- mainloop: double buffer, one sync per stage ----
    fill_stage(0, 0);
    __syncthreads();
    for (int t = 0; t < NT; t++) {
        const int cur = t & 1;
        if (t + 1 < NT) fill_stage(1 - cur, (t + 1) * BK);
        compute_stage(cur);
        __syncthreads();
    }

    // ---- epilogue ----
    const int g  = lane >> 2;
    const int kq = lane & 3;
    const float* be = bias + e * LDW;
    #pragma unroll
    for (int mt = 0; mt < 2; mt++) {
        const int lr0  = wm * 32 + mt * 16 + g;
        const int ent0 = toks[lr0];
        const int ent1 = toks[lr0 + 8];
        #pragma unroll
        for (int nn = 0; nn < 8; nn++) {
            const int c = n0 + wn * 64 + nn * 8 + 2 * kq;
            const float bb0 = be[c], bb1 = be[c + 1];
            if (!IS_FFN2) {
                if (ent0 >= 0) {
                    float v0 = acc[mt][nn][0] + bb0;
                    float v1 = acc[mt][nn][1] + bb1;
                    v0 = 0.5f * v0 * (1.f + erff(v0 * 0.70710678118654752f));
                    v1 = 0.5f * v1 * (1.f + erff(v1 * 0.70710678118654752f));
                    uint32_t h0, l0, h1, l1;
                    bsplit(v0, h0, l0); bsplit(v1, h1, l1);
                    const size_t o = ((size_t)ent0 * HH + c) * 2;
                    *(uint32_t*)((char*)g_hid_h + o) = h0 | (h1 << 16);
                    *(uint32_t*)((char*)g_hid_l + o) = l0 | (l1 << 16);
                }
                if (ent1 >= 0) {
                    float v0 = acc[mt][nn][2] + bb0;
                    float v1 = acc[mt][nn][3] + bb1;
                    v0 = 0.5f * v0 * (1.f + erff(v0 * 0.70710678118654752f));
                    v1 = 0.5f * v1 * (1.f + erff(v1 * 0.70710678118654752f));
                    uint32_t h0, l0, h1, l1;
                    bsplit(v0, h0, l0); bsplit(v1, h1, l1);
                    const size_t o = ((size_t)ent1 * HH + c) * 2;
                    *(uint32_t*)((char*)g_hid_h + o) = h0 | (h1 << 16);
                    *(uint32_t*)((char*)g_hid_l + o) = l0 | (l1 << 16);
                }
            } else {
                if (ent0 >= 0) {
                    const float w = wts[lr0];
                    float* o = outp + (size_t)(ent0 >> 1) * DD + c;
                    atomicAdd(o,     w * (acc[mt][nn][0] + bb0));
                    atomicAdd(o + 1, w * (acc[mt][nn][1] + bb1));
                }
                if (ent1 >= 0) {
                    const float w = wts[lr0 + 8];
                    float* o = outp + (size_t)(ent1 >> 1) * DD + c;
                    atomicAdd(o,     w * (acc[mt][nn][2] + bb0));
                    atomicAdd(o + 1, w * (acc[mt][nn][3] + bb1));
                }
            }
        }
    }
}

// ---------------------------------------------------------------------------
extern "C" void kernel_launch(void* const* d_in, const int* in_sizes, int n_in,
                              void* d_out, int out_size)
{
    const float* x    = (const float*)d_in[0];
    const float* dt   = (const float*)d_in[1];
    const float* dd   = (const float*)d_in[2];
    const float* dr   = (const float*)d_in[3];
    const float* de   = (const float*)d_in[4];
    const float* cemb = (const float*)d_in[5];
    const float* Wg   = (const float*)d_in[6];
    const float* bg   = (const float*)d_in[7];
    const float* Wn   = (const float*)d_in[8];
    const float* bn   = (const float*)d_in[9];
    const float* W1   = (const float*)d_in[10];
    const float* b1   = (const float*)d_in[11];
    const float* W2   = (const float*)d_in[12];
    const float* b2   = (const float*)d_in[13];
    const float* noise= (const float*)d_in[14];
    const int*   city = (const int*)d_in[15];

    float* out   = (float*)d_out;                       // (4096, 512)
    float* gate1 = (float*)d_out + (size_t)NTOK * DD;   // (4096, 10)

    cudaFuncSetAttribute((const void*)moe_mma_kernel<DD, HH, false>,
                         cudaFuncAttributeMaxDynamicSharedMemorySize, SMEM_DYN);
    cudaFuncSetAttribute((const void*)moe_mma_kernel<HH, DD, true>,
                         cudaFuncAttributeMaxDynamicSharedMemorySize, SMEM_DYN);

    cudaMemsetAsync(d_out, 0, (size_t)NTOK * DD * sizeof(float));
    zero_counts_kernel<<<1, 32>>>();

    router_kernel<<<NTOK / RTOK, 256>>>(x, dt, dd, dr, de, cemb, Wg, bg, Wn, bn,
                                        noise, city, gate1);

    dim3 grid1(HH / BN, NTOK / BM, EE);   // (16, 32, 10)
    moe_mma_kernel<DD, HH, false><<<grid1, 256, SMEM_DYN>>>(x, W1, b1, nullptr);

    dim3 grid2(DD / BN, NTOK / BM, EE);   // (4, 32, 10)
    moe_mma_kernel<HH, DD, true><<<grid2, 256, SMEM_DYN>>>(nullptr, W2, b2, out);
}

// round 7
// speedup vs baseline: 4.2523x; 1.5043x over previous
#include <cuda_runtime.h>
#include <cuda_bf16.h>
#include <math.h>
#include <stdint.h>

#define TT 1024
#define DD 512
#define EE 10
#define HH 2048
#define CEC 32
#define LIN 928
#define NTOK 4096
#define NPAIR 8192

#define BM 128
#define BN 128
#define BK 32           // bf16 k per stage

// A tile: 128 rows x 32 bf16, 80B pitch (conflict-free ldmatrix) = 10240B
// B tile: 32 k-rows x 128 bf16, 256B pitch, chunk-XOR swizzle = 8192B
#define A_TILE 10240
#define B_TILE 8192
#define OFF_AH 0
#define OFF_AL A_TILE
#define OFF_BH (2 * A_TILE)
#define OFF_BL (2 * A_TILE + B_TILE)
#define STAGE  (2 * A_TILE + 2 * B_TILE)   // 36864
#define SMEM_DYN (2 * STAGE)               // 73728

// Scratch (static device arrays — no allocation allowed)
__device__ __nv_bfloat16 g_hid_h[(size_t)NPAIR * HH];   // 32 MB
__device__ __nv_bfloat16 g_hid_l[(size_t)NPAIR * HH];   // 32 MB
__device__ int   g_count[EE];
__device__ int   g_entry[EE * NTOK];          // packed: token*2 + slot
__device__ float g_wt[EE * NTOK];

__global__ void zero_counts_kernel() {
    if (threadIdx.x < EE) g_count[threadIdx.x] = 0;
}

// ---------------------------------------------------------------------------
// helpers
// ---------------------------------------------------------------------------
__device__ __forceinline__ uint32_t sm_u32(const void* p) {
    return (uint32_t)__cvta_generic_to_shared(p);
}
__device__ __forceinline__ void bsplit(float v, uint32_t& h, uint32_t& l) {
    __nv_bfloat16 bh = __float2bfloat16_rn(v);
    h = (uint32_t)__bfloat16_as_ushort(bh);
    l = (uint32_t)__bfloat16_as_ushort(__float2bfloat16_rn(v - __bfloat162float(bh)));
}

#define MMA_BF16(d, a0, a1, a2, a3, b0, b1)                                   \
    asm volatile(                                                             \
        "mma.sync.aligned.m16n8k16.row.col.f32.bf16.bf16.f32 "                \
        "{%0,%1,%2,%3}, {%4,%5,%6,%7}, {%8,%9}, {%0,%1,%2,%3};"               \
        : "+f"((d)[0]), "+f"((d)[1]), "+f"((d)[2]), "+f"((d)[3])              \
        : "r"(a0), "r"(a1), "r"(a2), "r"(a3), "r"(b0), "r"(b1))

#define LDSM_X4(r0, r1, r2, r3, addr)                                         \
    asm volatile("ldmatrix.sync.aligned.m8n8.x4.shared.b16 {%0,%1,%2,%3}, [%4];" \
        : "=r"(r0), "=r"(r1), "=r"(r2), "=r"(r3) : "r"(addr))

#define LDSM_X4T(r0, r1, r2, r3, addr)                                        \
    asm volatile("ldmatrix.sync.aligned.m8n8.x4.trans.shared.b16 {%0,%1,%2,%3}, [%4];" \
        : "=r"(r0), "=r"(r1), "=r"(r2), "=r"(r3) : "r"(addr))

// ---------------------------------------------------------------------------
// Router: 32 tokens per block, weights staged in smem.
// ---------------------------------------------------------------------------
#define RTOK 32
#define RCH 116   // 928 / 8 chunks

__global__ __launch_bounds__(256)
void router_kernel(const float* __restrict__ x,
                   const float* __restrict__ dt,
                   const float* __restrict__ dd,
                   const float* __restrict__ dr,
                   const float* __restrict__ de,
                   const float* __restrict__ cemb,
                   const float* __restrict__ Wg,
                   const float* __restrict__ bg,
                   const float* __restrict__ Wn,
                   const float* __restrict__ bn,
                   const float* __restrict__ noise,
                   const int*   __restrict__ city,
                   float* __restrict__ gate1)
{
    __shared__ float Wsh[2 * EE][RCH];
    __shared__ float hsh[RTOK][RCH];
    __shared__ float lg[RTOK][2 * EE];

    const int tid = threadIdx.x;          // 256
    const int tb = blockIdx.x * RTOK;
    const int t = tid >> 3;               // token slot 0..31
    const int s = tid & 7;                // 0..7

    float acc0 = 0.f, acc1 = 0.f, acc2 = 0.f;

    for (int c = 0; c < 8; c++) {
        const int k0 = c * RCH;
        for (int i = tid; i < 2 * EE * RCH; i += 256) {
            int j = i / RCH, k = i % RCH;
            Wsh[j][k] = (j < EE) ? Wg[j * LIN + k0 + k] : Wn[(j - EE) * LIN + k0 + k];
        }
        for (int i = tid; i < RTOK * RCH; i += 256) {
            int tt = i / RCH, kk = i % RCH;
            int k = k0 + kk;
            int n = tb + tt;
            float v;
            if (k < DD)        v = x[n * DD + k];
            else if (k < 544)  v = cemb[city[n / TT] * CEC + (k - DD)];
            else if (k < 672)  v = dt[n * 128 + (k - 544)];
            else if (k < 800)  v = dd[n * 128 + (k - 672)];
            else if (k < 864)  v = dr[n * 64 + (k - 800)];
            else               v = de[n * 64 + (k - 864)];
            hsh[tt][kk] = v;
        }
        __syncthreads();
        for (int k = 0; k < RCH; k++) {
            float a = hsh[t][k];
            acc0 += a * Wsh[s][k];
            acc1 += a * Wsh[s + 8][k];
            if (s < 4) acc2 += a * Wsh[s + 16][k];
        }
        __syncthreads();
    }
    lg[t][s] = acc0;
    lg[t][s + 8] = acc1;
    if (s < 4) lg[t][s + 16] = acc2;
    __syncthreads();

    if (s == 0) {
        const int n = tb + t;
        float logits[EE], noisy[EE], ex[EE];
        float mx = -1e30f;
        for (int e = 0; e < EE; e++) { logits[e] = lg[t][e] + bg[e]; mx = fmaxf(mx, logits[e]); }
        float ssum = 0.f;
        for (int e = 0; e < EE; e++) { ex[e] = expf(logits[e] - mx); ssum += ex[e]; }
        const float rinv = 1.f / ssum;
        for (int e = 0; e < EE; e++) gate1[n * EE + e] = ex[e] * rinv;

        for (int e = 0; e < EE; e++) {
            const float z  = lg[t][EE + e] + bn[e];
            const float sp = fmaxf(z, 0.f) + log1pf(expf(-fabsf(z)));  // stable softplus
            noisy[e] = logits[e] + noise[n * EE + e] * sp;
        }
        int i0 = 0;
        for (int e = 1; e < EE; e++) if (noisy[e] > noisy[i0]) i0 = e;
        int i1 = (i0 == 0) ? 1 : 0;
        for (int e = 0; e < EE; e++) if (e != i0 && noisy[e] > noisy[i1]) i1 = e;

        const float m  = fmaxf(noisy[i0], noisy[i1]);
        const float s0 = expf(noisy[i0] - m), s1 = expf(noisy[i1] - m);
        const float inv = 1.f / (s0 + s1);

        int p0 = atomicAdd(&g_count[i0], 1);
        g_entry[i0 * NTOK + p0] = 2 * n;
        g_wt[i0 * NTOK + p0]    = s0 * inv;
        int p1 = atomicAdd(&g_count[i1], 1);
        g_entry[i1 * NTOK + p1] = 2 * n + 1;
        g_wt[i1 * NTOK + p1]    = s1 * inv;
    }
}

// ---------------------------------------------------------------------------
// Gathered expert GEMM: mma.sync m16n8k16 bf16, 3xBF16 split, fp32 accum.
//   IS_FFN2 == false: hid(hi,lo)[pair] = split(gelu(x[tok] @ W1[e] + b1[e]))
//   IS_FFN2 == true : out[tok] += w * (hid[pair] @ W2[e] + b2[e])
// Block 128x128, BK=32 (2 k-steps of 16), 8 warps 4x2, warp tile 32x64.
// A smem [m][k] 80B pitch; B smem [k][n] 256B pitch, chunk c ^= (k&7).
// 2 CTAs/SM (register-capped) to cover MMA dependency + barrier latency.
// ---------------------------------------------------------------------------
template<int KTOT, int LDW, bool IS_FFN2>
__global__ __launch_bounds__(256, 2)
void moe_mma_kernel(const float* __restrict__ Asrc,
                    const float* __restrict__ W,
                    const float* __restrict__ bias,
                    float* __restrict__ outp)
{
    constexpr int NT = KTOT / BK;
    const int e  = blockIdx.z;
    const int m0 = blockIdx.y * BM;
    const int n0 = blockIdx.x * BN;
    const int L  = g_count[e];
    if (m0 >= L) return;

    extern __shared__ char smem[];
    __shared__ int   toks[BM];
    __shared__ float wts[BM];

    const int tid  = threadIdx.x;
    const int wid  = tid >> 5;
    const int lane = tid & 31;

    if (tid < BM) {
        int i = m0 + tid;
        toks[tid] = (i < L) ? g_entry[e * NTOK + i] : -1;
        wts[tid]  = (IS_FFN2 && i < L) ? g_wt[e * NTOK + i] : 0.f;
    }
    __syncthreads();

    const float* Wp = W + (size_t)e * KTOT * LDW + n0;

    // ---- fills ----
    auto fill_stage = [&](int buf, int k0) {
        char* st = smem + buf * STAGE;
        // A: 128 rows x 4 chunks of 8; two passes
        #pragma unroll
        for (int p = 0; p < 2; p++) {
            const int idx = p * 256 + tid;
            const int r = idx >> 2, c = idx & 3;
            const int ent = toks[r];
            uint4 hp = make_uint4(0, 0, 0, 0), lp = hp;
            if (ent >= 0) {
                if (IS_FFN2) {
                    const size_t o = ((size_t)ent * KTOT + k0 + c * 8) * 2;
                    hp = *(const uint4*)((const char*)g_hid_h + o);
                    lp = *(const uint4*)((const char*)g_hid_l + o);
                } else {
                    const float* ar = Asrc + (size_t)(ent >> 1) * KTOT + k0 + c * 8;
                    float4 v0 = *(const float4*)ar;
                    float4 v1 = *(const float4*)(ar + 4);
                    uint32_t h[8], l[8];
                    bsplit(v0.x, h[0], l[0]); bsplit(v0.y, h[1], l[1]);
                    bsplit(v0.z, h[2], l[2]); bsplit(v0.w, h[3], l[3]);
                    bsplit(v1.x, h[4], l[4]); bsplit(v1.y, h[5], l[5]);
                    bsplit(v1.z, h[6], l[6]); bsplit(v1.w, h[7], l[7]);
                    hp = make_uint4(h[0] | (h[1] << 16), h[2] | (h[3] << 16),
                                    h[4] | (h[5] << 16), h[6] | (h[7] << 16));
                    lp = make_uint4(l[0] | (l[1] << 16), l[2] | (l[3] << 16),
                                    l[4] | (l[5] << 16), l[6] | (l[7] << 16));
                }
            }
            *(uint4*)(st + OFF_AH + r * 80 + c * 16) = hp;
            *(uint4*)(st + OFF_AL + r * 80 + c * 16) = lp;
        }
        // B: 32 k-rows x 16 chunks of 8; two passes
        #pragma unroll
        for (int p = 0; p < 2; p++) {
            const int idx = p * 256 + tid;
            const int k = idx >> 4, c = idx & 15;
            const float* wr = Wp + (size_t)(k0 + k) * LDW + c * 8;
            float4 v0 = *(const float4*)wr;
            float4 v1 = *(const float4*)(wr + 4);
            uint32_t h[8], l[8];
            bsplit(v0.x, h[0], l[0]); bsplit(v0.y, h[1], l[1]);
            bsplit(v0.z, h[2], l[2]); bsplit(v0.w, h[3], l[3]);
            bsplit(v1.x, h[4], l[4]); bsplit(v1.y, h[5], l[5]);
            bsplit(v1.z, h[6], l[6]); bsplit(v1.w, h[7], l[7]);
            uint4 hp = make_uint4(h[0] | (h[1] << 16), h[2] | (h[3] << 16),
                                  h[4] | (h[5] << 16), h[6] | (h[7] << 16));
            uint4 lp = make_uint4(l[0] | (l[1] << 16), l[2] | (l[3] << 16),
                                  l[4] | (l[5] << 16), l[6] | (l[7] << 16));
            const int off = k * 256 + ((c ^ (k & 7)) * 16);
            *(uint4*)(st + OFF_BH + off) = hp;
            *(uint4*)(st + OFF_BL + off) = lp;
        }
    };

    // ---- accumulators ----
    const int wm = wid >> 1, wn = wid & 1;
    float acc[2][8][4];
    #pragma unroll
    for (int mt = 0; mt < 2; mt++)
        #pragma unroll
        for (int nn = 0; nn < 8; nn++)
            #pragma unroll
            for (int i = 0; i < 4; i++) acc[mt][nn][i] = 0.f;

    auto compute_stage = [&](int buf) {
        char* st = smem + buf * STAGE;
        const uint32_t ah = sm_u32(st + OFF_AH);
        const uint32_t al = sm_u32(st + OFF_AL);
        const uint32_t bh = sm_u32(st + OFF_BH);
        const uint32_t bl = sm_u32(st + OFF_BL);
        #pragma unroll
        for (int ks = 0; ks < 2; ks++) {
            // A frags: rows lane&15, k-half lane>>4
            uint32_t a_h[2][4], a_l[2][4];
            #pragma unroll
            for (int mt = 0; mt < 2; mt++) {
                const uint32_t ao = (wm * 32 + mt * 16 + (lane & 15)) * 80
                                  + ks * 32 + (lane >> 4) * 16;
                LDSM_X4(a_h[mt][0], a_h[mt][1], a_h[mt][2], a_h[mt][3], ah + ao);
                LDSM_X4(a_l[mt][0], a_l[mt][1], a_l[mt][2], a_l[mt][3], al + ao);
            }
            // B frags loaded per-bt to cap live registers (2 CTAs/SM target)
            #pragma unroll
            for (int bt = 0; bt < 4; bt++) {
                uint32_t bfh[4], bfl[4];
                const int k = ks * 16 + (lane & 15);
                const int c = ((wn * 64 + bt * 16) >> 3) + (lane >> 4);
                const uint32_t bo = k * 256 + ((c ^ (lane & 7)) * 16);
                LDSM_X4T(bfh[0], bfh[1], bfh[2], bfh[3], bh + bo);
                LDSM_X4T(bfl[0], bfl[1], bfl[2], bfl[3], bl + bo);
                #pragma unroll
                for (int mt = 0; mt < 2; mt++) {
                    float* d0 = acc[mt][2 * bt];
                    float* d1 = acc[mt][2 * bt + 1];
                    MMA_BF16(d0, a_h[mt][0], a_h[mt][1], a_h[mt][2], a_h[mt][3],
                             bfh[0], bfh[1]);
                    MMA_BF16(d0, a_h[mt][0], a_h[mt][1], a_h[mt][2], a_h[mt][3],
                             bfl[0], bfl[1]);
                    MMA_BF16(d0, a_l[mt][0], a_l[mt][1], a_l[mt][2], a_l[mt][3],
                             bfh[0], bfh[1]);
                    MMA_BF16(d1, a_h[mt][0], a_h[mt][1], a_h[mt][2], a_h[mt][3],
                             bfh[2], bfh[3]);
                    MMA_BF16(d1, a_h[mt][0], a_h[mt][1], a_h[mt][2], a_h[mt][3],
                             bfl[2], bfl[3]);
                    MMA_BF16(d1, a_l[mt][0], a_l[mt][1], a_l[mt][2], a_l[mt][3],
                             bfh[2], bfh[3]);
                }
            }
        }
    };

    // ---- mainloop: double buffer, one sync per stage ----
    fill_stage(0, 0);
    __syncthreads();
    for (int t = 0; t < NT; t++) {
        const int cur = t & 1;
        if (t + 1 < NT) fill_stage(1 - cur, (t + 1) * BK);
        compute_stage(cur);
        __syncthreads();
    }

    // ---- epilogue ----
    const int g  = lane >> 2;
    const int kq = lane & 3;
    const float* be = bias + e * LDW;
    #pragma unroll
    for (int mt = 0; mt < 2; mt++) {
        const int lr0  = wm * 32 + mt * 16 + g;
        const int ent0 = toks[lr0];
        const int ent1 = toks[lr0 + 8];
        #pragma unroll
        for (int nn = 0; nn < 8; nn++) {
            const int c = n0 + wn * 64 + nn * 8 + 2 * kq;
            const float bb0 = be[c], bb1 = be[c + 1];
            if (!IS_FFN2) {
                if (ent0 >= 0) {
                    float v0 = acc[mt][nn][0] + bb0;
                    float v1 = acc[mt][nn][1] + bb1;
                    v0 = 0.5f * v0 * (1.f + erff(v0 * 0.70710678118654752f));
                    v1 = 0.5f * v1 * (1.f + erff(v1 * 0.70710678118654752f));
                    uint32_t h0, l0, h1, l1;
                    bsplit(v0, h0, l0); bsplit(v1, h1, l1);
                    const size_t o = ((size_t)ent0 * HH + c) * 2;
                    *(uint32_t*)((char*)g_hid_h + o) = h0 | (h1 << 16);
                    *(uint32_t*)((char*)g_hid_l + o) = l0 | (l1 << 16);
                }
                if (ent1 >= 0) {
                    float v0 = acc[mt][nn][2] + bb0;
                    float v1 = acc[mt][nn][3] + bb1;
                    v0 = 0.5f * v0 * (1.f + erff(v0 * 0.70710678118654752f));
                    v1 = 0.5f * v1 * (1.f + erff(v1 * 0.70710678118654752f));
                    uint32_t h0, l0, h1, l1;
                    bsplit(v0, h0, l0); bsplit(v1, h1, l1);
                    const size_t o = ((size_t)ent1 * HH + c) * 2;
                    *(uint32_t*)((char*)g_hid_h + o) = h0 | (h1 << 16);
                    *(uint32_t*)((char*)g_hid_l + o) = l0 | (l1 << 16);
                }
            } else {
                if (ent0 >= 0) {
                    const float w = wts[lr0];
                    float* o = outp + (size_t)(ent0 >> 1) * DD + c;
                    atomicAdd(o,     w * (acc[mt][nn][0] + bb0));
                    atomicAdd(o + 1, w * (acc[mt][nn][1] + bb1));
                }
                if (ent1 >= 0) {
                    const float w = wts[lr0 + 8];
                    float* o = outp + (size_t)(ent1 >> 1) * DD + c;
                    atomicAdd(o,     w * (acc[mt][nn][2] + bb0));
                    atomicAdd(o + 1, w * (acc[mt][nn][3] + bb1));
                }
            }
        }
    }
}

// ---------------------------------------------------------------------------
extern "C" void kernel_launch(void* const* d_in, const int* in_sizes, int n_in,
                              void* d_out, int out_size)
{
    const float* x    = (const float*)d_in[0];
    const float* dt   = (const float*)d_in[1];
    const float* dd   = (const float*)d_in[2];
    const float* dr   = (const float*)d_in[3];
    const float* de   = (const float*)d_in[4];
    const float* cemb = (const float*)d_in[5];
    const float* Wg   = (const float*)d_in[6];
    const float* bg   = (const float*)d_in[7];
    const float* Wn   = (const float*)d_in[8];
    const float* bn   = (const float*)d_in[9];
    const float* W1   = (const float*)d_in[10];
    const float* b1   = (const float*)d_in[11];
    const float* W2   = (const float*)d_in[12];
    const float* b2   = (const float*)d_in[13];
    const float* noise= (const float*)d_in[14];
    const int*   city = (const int*)d_in[15];

    float* out   = (float*)d_out;                       // (4096, 512)
    float* gate1 = (float*)d_out + (size_t)NTOK * DD;   // (4096, 10)

    cudaFuncSetAttribute((const void*)moe_mma_kernel<DD, HH, false>,
                         cudaFuncAttributeMaxDynamicSharedMemorySize, SMEM_DYN);
    cudaFuncSetAttribute((const void*)moe_mma_kernel<HH, DD, true>,
                         cudaFuncAttributeMaxDynamicSharedMemorySize, SMEM_DYN);

    cudaMemsetAsync(d_out, 0, (size_t)NTOK * DD * sizeof(float));
    zero_counts_kernel<<<1, 32>>>();

    router_kernel<<<NTOK / RTOK, 256>>>(x, dt, dd, dr, de, cemb, Wg, bg, Wn, bn,
                                        noise, city, gate1);

    dim3 grid1(HH / BN, NTOK / BM, EE);   // (16, 32, 10)
    moe_mma_kernel<DD, HH, false><<<grid1, 256, SMEM_DYN>>>(x, W1, b1, nullptr);

    dim3 grid2(DD / BN, NTOK / BM, EE);   // (4, 32, 10)
    moe_mma_kernel<HH, DD, true><<<grid2, 256, SMEM_DYN>>>(nullptr, W2, b2, out);
}

// round 8
// speedup vs baseline: 4.2525x; 1.0001x over previous
#include <cuda_runtime.h>
#include <cuda_bf16.h>
#include <math.h>
#include <stdint.h>

#define TT 1024
#define DD 512
#define EE 10
#define HH 2048
#define CEC 32
#define LIN 928
#define NTOK 4096
#define NPAIR 8192

#define BM 128
#define BN 128
#define BK 32           // bf16 k per stage

// A tile: 128 rows x 32 bf16, 80B pitch (conflict-free ldmatrix) = 10240B
// B tile: 32 k-rows x 128 bf16, 256B pitch, chunk-XOR swizzle = 8192B
#define A_TILE 10240
#define B_TILE 8192
#define OFF_AH 0
#define OFF_AL A_TILE
#define OFF_BH (2 * A_TILE)
#define OFF_BL (2 * A_TILE + B_TILE)
#define STAGE  (2 * A_TILE + 2 * B_TILE)   // 36864
#define SMEM_DYN (2 * STAGE)               // 73728

// Scratch (static device arrays — no allocation allowed)
__device__ __nv_bfloat16 g_hid_h[(size_t)NPAIR * HH];   // 32 MB
__device__ __nv_bfloat16 g_hid_l[(size_t)NPAIR * HH];   // 32 MB
__device__ int   g_count[EE];
__device__ int   g_entry[EE * NTOK];          // packed: token*2 + slot
__device__ float g_wt[EE * NTOK];

__global__ void zero_counts_kernel() {
    if (threadIdx.x < EE) g_count[threadIdx.x] = 0;
}

// ---------------------------------------------------------------------------
// helpers
// ---------------------------------------------------------------------------
__device__ __forceinline__ uint32_t sm_u32(const void* p) {
    return (uint32_t)__cvta_generic_to_shared(p);
}
__device__ __forceinline__ void bsplit(float v, uint32_t& h, uint32_t& l) {
    __nv_bfloat16 bh = __float2bfloat16_rn(v);
    h = (uint32_t)__bfloat16_as_ushort(bh);
    l = (uint32_t)__bfloat16_as_ushort(__float2bfloat16_rn(v - __bfloat162float(bh)));
}

#define MMA_BF16(d, a0, a1, a2, a3, b0, b1)                                   \
    asm volatile(                                                             \
        "mma.sync.aligned.m16n8k16.row.col.f32.bf16.bf16.f32 "                \
        "{%0,%1,%2,%3}, {%4,%5,%6,%7}, {%8,%9}, {%0,%1,%2,%3};"               \
        : "+f"((d)[0]), "+f"((d)[1]), "+f"((d)[2]), "+f"((d)[3])              \
        : "r"(a0), "r"(a1), "r"(a2), "r"(a3), "r"(b0), "r"(b1))

#define LDSM_X4(r0, r1, r2, r3, addr)                                         \
    asm volatile("ldmatrix.sync.aligned.m8n8.x4.shared.b16 {%0,%1,%2,%3}, [%4];" \
        : "=r"(r0), "=r"(r1), "=r"(r2), "=r"(r3) : "r"(addr))

#define LDSM_X4T(r0, r1, r2, r3, addr)                                        \
    asm volatile("ldmatrix.sync.aligned.m8n8.x4.trans.shared.b16 {%0,%1,%2,%3}, [%4];" \
        : "=r"(r0), "=r"(r1), "=r"(r2), "=r"(r3) : "r"(addr))

// ---------------------------------------------------------------------------
// Router: 32 tokens per block, weights staged in smem.
// ---------------------------------------------------------------------------
#define RTOK 32
#define RCH 116   // 928 / 8 chunks

__global__ __launch_bounds__(256)
void router_kernel(const float* __restrict__ x,
                   const float* __restrict__ dt,
                   const float* __restrict__ dd,
                   const float* __restrict__ dr,
                   const float* __restrict__ de,
                   const float* __restrict__ cemb,
                   const float* __restrict__ Wg,
                   const float* __restrict__ bg,
                   const float* __restrict__ Wn,
                   const float* __restrict__ bn,
                   const float* __restrict__ noise,
                   const int*   __restrict__ city,
                   float* __restrict__ gate1)
{
    __shared__ float Wsh[2 * EE][RCH];
    __shared__ float hsh[RTOK][RCH];
    __shared__ float lg[RTOK][2 * EE];

    const int tid = threadIdx.x;          // 256
    const int tb = blockIdx.x * RTOK;
    const int t = tid >> 3;               // token slot 0..31
    const int s = tid & 7;                // 0..7

    float acc0 = 0.f, acc1 = 0.f, acc2 = 0.f;

    for (int c = 0; c < 8; c++) {
        const int k0 = c * RCH;
        for (int i = tid; i < 2 * EE * RCH; i += 256) {
            int j = i / RCH, k = i % RCH;
            Wsh[j][k] = (j < EE) ? Wg[j * LIN + k0 + k] : Wn[(j - EE) * LIN + k0 + k];
        }
        for (int i = tid; i < RTOK * RCH; i += 256) {
            int tt = i / RCH, kk = i % RCH;
            int k = k0 + kk;
            int n = tb + tt;
            float v;
            if (k < DD)        v = x[n * DD + k];
            else if (k < 544)  v = cemb[city[n / TT] * CEC + (k - DD)];
            else if (k < 672)  v = dt[n * 128 + (k - 544)];
            else if (k < 800)  v = dd[n * 128 + (k - 672)];
            else if (k < 864)  v = dr[n * 64 + (k - 800)];
            else               v = de[n * 64 + (k - 864)];
            hsh[tt][kk] = v;
        }
        __syncthreads();
        for (int k = 0; k < RCH; k++) {
            float a = hsh[t][k];
            acc0 += a * Wsh[s][k];
            acc1 += a * Wsh[s + 8][k];
            if (s < 4) acc2 += a * Wsh[s + 16][k];
        }
        __syncthreads();
    }
    lg[t][s] = acc0;
    lg[t][s + 8] = acc1;
    if (s < 4) lg[t][s + 16] = acc2;
    __syncthreads();

    if (s == 0) {
        const int n = tb + t;
        float logits[EE], noisy[EE], ex[EE];
        float mx = -1e30f;
        for (int e = 0; e < EE; e++) { logits[e] = lg[t][e] + bg[e]; mx = fmaxf(mx, logits[e]); }
        float ssum = 0.f;
        for (int e = 0; e < EE; e++) { ex[e] = expf(logits[e] - mx); ssum += ex[e]; }
        const float rinv = 1.f / ssum;
        for (int e = 0; e < EE; e++) gate1[n * EE + e] = ex[e] * rinv;

        for (int e = 0; e < EE; e++) {
            const float z  = lg[t][EE + e] + bn[e];
            const float sp = fmaxf(z, 0.f) + log1pf(expf(-fabsf(z)));  // stable softplus
            noisy[e] = logits[e] + noise[n * EE + e] * sp;
        }
        int i0 = 0;
        for (int e = 1; e < EE; e++) if (noisy[e] > noisy[i0]) i0 = e;
        int i1 = (i0 == 0) ? 1 : 0;
        for (int e = 0; e < EE; e++) if (e != i0 && noisy[e] > noisy[i1]) i1 = e;

        const float m  = fmaxf(noisy[i0], noisy[i1]);
        const float s0 = expf(noisy[i0] - m), s1 = expf(noisy[i1] - m);
        const float inv = 1.f / (s0 + s1);

        int p0 = atomicAdd(&g_count[i0], 1);
        g_entry[i0 * NTOK + p0] = 2 * n;
        g_wt[i0 * NTOK + p0]    = s0 * inv;
        int p1 = atomicAdd(&g_count[i1], 1);
        g_entry[i1 * NTOK + p1] = 2 * n + 1;
        g_wt[i1 * NTOK + p1]    = s1 * inv;
    }
}

// ---------------------------------------------------------------------------
// Gathered expert GEMM: mma.sync m16n8k16 bf16, 3xBF16 split, fp32 accum.
//   IS_FFN2 == false: hid(hi,lo)[pair] = split(gelu(x[tok] @ W1[e] + b1[e]))
//   IS_FFN2 == true : out[tok] += w * (hid[pair] @ W2[e] + b2[e])
// Block 128x128, BK=32 (2 k-steps of 16), 8 warps 4x2, warp tile 32x64.
// A smem [m][k] 80B pitch; B smem [k][n] 256B pitch, chunk c ^= (k&7).
// 2 CTAs/SM (register-capped) to cover MMA dependency + barrier latency.
// ---------------------------------------------------------------------------
template<int KTOT, int LDW, bool IS_FFN2>
__global__ __launch_bounds__(256, 2)
void moe_mma_kernel(const float* __restrict__ Asrc,
                    const float* __restrict__ W,
                    const float* __restrict__ bias,
                    float* __restrict__ outp)
{
    constexpr int NT = KTOT / BK;
    const int e  = blockIdx.z;
    const int m0 = blockIdx.y * BM;
    const int n0 = blockIdx.x * BN;
    const int L  = g_count[e];
    if (m0 >= L) return;

    extern __shared__ char smem[];
    __shared__ int   toks[BM];
    __shared__ float wts[BM];

    const int tid  = threadIdx.x;
    const int wid  = tid >> 5;
    const int lane = tid & 31;

    if (tid < BM) {
        int i = m0 + tid;
        toks[tid] = (i < L) ? g_entry[e * NTOK + i] : -1;
        wts[tid]  = (IS_FFN2 && i < L) ? g_wt[e * NTOK + i] : 0.f;
    }
    __syncthreads();

    const float* Wp = W + (size_t)e * KTOT * LDW + n0;

    // ---- fills ----
    auto fill_stage = [&](int buf, int k0) {
        char* st = smem + buf * STAGE;
        // A: 128 rows x 4 chunks of 8; two passes
        #pragma unroll
        for (int p = 0; p < 2; p++) {
            const int idx = p * 256 + tid;
            const int r = idx >> 2, c = idx & 3;
            const int ent = toks[r];
            uint4 hp = make_uint4(0, 0, 0, 0), lp = hp;
            if (ent >= 0) {
                if (IS_FFN2) {
                    const size_t o = ((size_t)ent * KTOT + k0 + c * 8) * 2;
                    hp = *(const uint4*)((const char*)g_hid_h + o);
                    lp = *(const uint4*)((const char*)g_hid_l + o);
                } else {
                    const float* ar = Asrc + (size_t)(ent >> 1) * KTOT + k0 + c * 8;
                    float4 v0 = *(const float4*)ar;
                    float4 v1 = *(const float4*)(ar + 4);
                    uint32_t h[8], l[8];
                    bsplit(v0.x, h[0], l[0]); bsplit(v0.y, h[1], l[1]);
                    bsplit(v0.z, h[2], l[2]); bsplit(v0.w, h[3], l[3]);
                    bsplit(v1.x, h[4], l[4]); bsplit(v1.y, h[5], l[5]);
                    bsplit(v1.z, h[6], l[6]); bsplit(v1.w, h[7], l[7]);
                    hp = make_uint4(h[0] | (h[1] << 16), h[2] | (h[3] << 16),
                                    h[4] | (h[5] << 16), h[6] | (h[7] << 16));
                    lp = make_uint4(l[0] | (l[1] << 16), l[2] | (l[3] << 16),
                                    l[4] | (l[5] << 16), l[6] | (l[7] << 16));
                }
            }
            *(uint4*)(st + OFF_AH + r * 80 + c * 16) = hp;
            *(uint4*)(st + OFF_AL + r * 80 + c * 16) = lp;
        }
        // B: 32 k-rows x 16 chunks of 8; two passes
        #pragma unroll
        for (int p = 0; p < 2; p++) {
            const int idx = p * 256 + tid;
            const int k = idx >> 4, c = idx & 15;
            const float* wr = Wp + (size_t)(k0 + k) * LDW + c * 8;
            float4 v0 = *(const float4*)wr;
            float4 v1 = *(const float4*)(wr + 4);
            uint32_t h[8], l[8];
            bsplit(v0.x, h[0], l[0]); bsplit(v0.y, h[1], l[1]);
            bsplit(v0.z, h[2], l[2]); bsplit(v0.w, h[3], l[3]);
            bsplit(v1.x, h[4], l[4]); bsplit(v1.y, h[5], l[5]);
            bsplit(v1.z, h[6], l[6]); bsplit(v1.w, h[7], l[7]);
            uint4 hp = make_uint4(h[0] | (h[1] << 16), h[2] | (h[3] << 16),
                                  h[4] | (h[5] << 16), h[6] | (h[7] << 16));
            uint4 lp = make_uint4(l[0] | (l[1] << 16), l[2] | (l[3] << 16),
                                  l[4] | (l[5] << 16), l[6] | (l[7] << 16));
            const int off = k * 256 + ((c ^ (k & 7)) * 16);
            *(uint4*)(st + OFF_BH + off) = hp;
            *(uint4*)(st + OFF_BL + off) = lp;
        }
    };

    // ---- accumulators ----
    const int wm = wid >> 1, wn = wid & 1;
    float acc[2][8][4];
    #pragma unroll
    for (int mt = 0; mt < 2; mt++)
        #pragma unroll
        for (int nn = 0; nn < 8; nn++)
            #pragma unroll
            for (int i = 0; i < 4; i++) acc[mt][nn][i] = 0.f;

    auto compute_stage = [&](int buf) {
        char* st = smem + buf * STAGE;
        const uint32_t ah = sm_u32(st + OFF_AH);
        const uint32_t al = sm_u32(st + OFF_AL);
        const uint32_t bh = sm_u32(st + OFF_BH);
        const uint32_t bl = sm_u32(st + OFF_BL);
        #pragma unroll
        for (int ks = 0; ks < 2; ks++) {
            // A frags: rows lane&15, k-half lane>>4
            uint32_t a_h[2][4], a_l[2][4];
            #pragma unroll
            for (int mt = 0; mt < 2; mt++) {
                const uint32_t ao = (wm * 32 + mt * 16 + (lane & 15)) * 80
                                  + ks * 32 + (lane >> 4) * 16;
                LDSM_X4(a_h[mt][0], a_h[mt][1], a_h[mt][2], a_h[mt][3], ah + ao);
                LDSM_X4(a_l[mt][0], a_l[mt][1], a_l[mt][2], a_l[mt][3], al + ao);
            }
            // B frags loaded per-bt to cap live registers (2 CTAs/SM target)
            #pragma unroll
            for (int bt = 0; bt < 4; bt++) {
                uint32_t bfh[4], bfl[4];
                const int k = ks * 16 + (lane & 15);
                const int c = ((wn * 64 + bt * 16) >> 3) + (lane >> 4);
                const uint32_t bo = k * 256 + ((c ^ (lane & 7)) * 16);
                LDSM_X4T(bfh[0], bfh[1], bfh[2], bfh[3], bh + bo);
                LDSM_X4T(bfl[0], bfl[1], bfl[2], bfl[3], bl + bo);
                #pragma unroll
                for (int mt = 0; mt < 2; mt++) {
                    float* d0 = acc[mt][2 * bt];
                    float* d1 = acc[mt][2 * bt + 1];
                    MMA_BF16(d0, a_h[mt][0], a_h[mt][1], a_h[mt][2], a_h[mt][3],
                             bfh[0], bfh[1]);
                    MMA_BF16(d0, a_h[mt][0], a_h[mt][1], a_h[mt][2], a_h[mt][3],
                             bfl[0], bfl[1]);
                    MMA_BF16(d0, a_l[mt][0], a_l[mt][1], a_l[mt][2], a_l[mt][3],
                             bfh[0], bfh[1]);
                    MMA_BF16(d1, a_h[mt][0], a_h[mt][1], a_h[mt][2], a_h[mt][3],
                             bfh[2], bfh[3]);
                    MMA_BF16(d1, a_h[mt][0], a_h[mt][1], a_h[mt][2], a_h[mt][3],
                             bfl[2], bfl[3]);
                    MMA_BF16(d1, a_l[mt][0], a_l[mt][1], a_l[mt][2], a_l[mt][3],
                             bfh[2], bfh[3]);
                }
            }
        }
    };

    // ---- mainloop: double buffer, one sync per stage ----
    fill_stage(0, 0);
    __syncthreads();
    for (int t = 0; t < NT; t++) {
        const int cur = t & 1;
        if (t + 1 < NT) fill_stage(1 - cur, (t + 1) * BK);
        compute_stage(cur);
        __syncthreads();
    }

    // ---- epilogue ----
    const int g  = lane >> 2;
    const int kq = lane & 3;
    const float* be = bias + e * LDW;
    #pragma unroll
    for (int mt = 0; mt < 2; mt++) {
        const int lr0  = wm * 32 + mt * 16 + g;
        const int ent0 = toks[lr0];
        const int ent1 = toks[lr0 + 8];
        #pragma unroll
        for (int nn = 0; nn < 8; nn++) {
            const int c = n0 + wn * 64 + nn * 8 + 2 * kq;
            const float bb0 = be[c], bb1 = be[c + 1];
            if (!IS_FFN2) {
                if (ent0 >= 0) {
                    float v0 = acc[mt][nn][0] + bb0;
                    float v1 = acc[mt][nn][1] + bb1;
                    v0 = 0.5f * v0 * (1.f + erff(v0 * 0.70710678118654752f));
                    v1 = 0.5f * v1 * (1.f + erff(v1 * 0.70710678118654752f));
                    uint32_t h0, l0, h1, l1;
                    bsplit(v0, h0, l0); bsplit(v1, h1, l1);
                    const size_t o = ((size_t)ent0 * HH + c) * 2;
                    *(uint32_t*)((char*)g_hid_h + o) = h0 | (h1 << 16);
                    *(uint32_t*)((char*)g_hid_l + o) = l0 | (l1 << 16);
                }
                if (ent1 >= 0) {
                    float v0 = acc[mt][nn][2] + bb0;
                    float v1 = acc[mt][nn][3] + bb1;
                    v0 = 0.5f * v0 * (1.f + erff(v0 * 0.70710678118654752f));
                    v1 = 0.5f * v1 * (1.f + erff(v1 * 0.70710678118654752f));
                    uint32_t h0, l0, h1, l1;
                    bsplit(v0, h0, l0); bsplit(v1, h1, l1);
                    const size_t o = ((size_t)ent1 * HH + c) * 2;
                    *(uint32_t*)((char*)g_hid_h + o) = h0 | (h1 << 16);
                    *(uint32_t*)((char*)g_hid_l + o) = l0 | (l1 << 16);
                }
            } else {
                if (ent0 >= 0) {
                    const float w = wts[lr0];
                    float* o = outp + (size_t)(ent0 >> 1) * DD + c;
                    atomicAdd(o,     w * (acc[mt][nn][0] + bb0));
                    atomicAdd(o + 1, w * (acc[mt][nn][1] + bb1));
                }
                if (ent1 >= 0) {
                    const float w = wts[lr0 + 8];
                    float* o = outp + (size_t)(ent1 >> 1) * DD + c;
                    atomicAdd(o,     w * (acc[mt][nn][2] + bb0));
                    atomicAdd(o + 1, w * (acc[mt][nn][3] + bb1));
                }
            }
        }
    }
}

// ---------------------------------------------------------------------------
extern "C" void kernel_launch(void* const* d_in, const int* in_sizes, int n_in,
                              void* d_out, int out_size)
{
    const float* x    = (const float*)d_in[0];
    const float* dt   = (const float*)d_in[1];
    const float* dd   = (const float*)d_in[2];
    const float* dr   = (const float*)d_in[3];
    const float* de   = (const float*)d_in[4];
    const float* cemb = (const float*)d_in[5];
    const float* Wg   = (const float*)d_in[6];
    const float* bg   = (const float*)d_in[7];
    const float* Wn   = (const float*)d_in[8];
    const float* bn   = (const float*)d_in[9];
    const float* W1   = (const float*)d_in[10];
    const float* b1   = (const float*)d_in[11];
    const float* W2   = (const float*)d_in[12];
    const float* b2   = (const float*)d_in[13];
    const float* noise= (const float*)d_in[14];
    const int*   city = (const int*)d_in[15];

    float* out   = (float*)d_out;                       // (4096, 512)
    float* gate1 = (float*)d_out + (size_t)NTOK * DD;   // (4096, 10)

    cudaFuncSetAttribute((const void*)moe_mma_kernel<DD, HH, false>,
                         cudaFuncAttributeMaxDynamicSharedMemorySize, SMEM_DYN);
    cudaFuncSetAttribute((const void*)moe_mma_kernel<HH, DD, true>,
                         cudaFuncAttributeMaxDynamicSharedMemorySize, SMEM_DYN);

    cudaMemsetAsync(d_out, 0, (size_t)NTOK * DD * sizeof(float));
    zero_counts_kernel<<<1, 32>>>();

    router_kernel<<<NTOK / RTOK, 256>>>(x, dt, dd, dr, de, cemb, Wg, bg, Wn, bn,
                                        noise, city, gate1);

    dim3 grid1(HH / BN, NTOK / BM, EE);   // (16, 32, 10)
    moe_mma_kernel<DD, HH, false><<<grid1, 256, SMEM_DYN>>>(x, W1, b1, nullptr);

    dim3 grid2(DD / BN, NTOK / BM, EE);   // (4, 32, 10)
    moe_mma_kernel<HH, DD, true><<<grid2, 256, SMEM_DYN>>>(nullptr, W2, b2, out);
}

// round 9
// speedup vs baseline: 4.5655x; 1.0736x over previous
#include <cuda_runtime.h>
#include <cuda_bf16.h>
#include <math.h>
#include <stdint.h>

#define TT 1024
#define DD 512
#define EE 10
#define HH 2048
#define CEC 32
#define LIN 928
#define NTOK 4096
#define NPAIR 8192

#define BM 128
#define BN 128
#define BK 32           // bf16 k per stage

// A tile: 128 rows x 32 bf16, 80B pitch (conflict-free ldmatrix) = 10240B
// B tile: 32 k-rows x 128 bf16, 256B pitch, chunk-XOR swizzle = 8192B
#define A_TILE 10240
#define B_TILE 8192
#define OFF_AH 0
#define OFF_AL A_TILE
#define OFF_BH (2 * A_TILE)
#define OFF_BL (2 * A_TILE + B_TILE)
#define STAGE  (2 * A_TILE + 2 * B_TILE)   // 36864
#define SMEM_DYN (2 * STAGE)               // 73728

// Scratch (static device arrays — no allocation allowed)
__device__ __align__(16) __nv_bfloat16 g_hid_h[(size_t)NPAIR * HH];   // 32 MB
__device__ __align__(16) __nv_bfloat16 g_hid_l[(size_t)NPAIR * HH];   // 32 MB
__device__ __align__(16) __nv_bfloat16 g_xh[(size_t)NTOK * DD];
__device__ __align__(16) __nv_bfloat16 g_xl[(size_t)NTOK * DD];
__device__ __align__(16) __nv_bfloat16 g_w1h[(size_t)EE * DD * HH];
__device__ __align__(16) __nv_bfloat16 g_w1l[(size_t)EE * DD * HH];
__device__ __align__(16) __nv_bfloat16 g_w2h[(size_t)EE * HH * DD];
__device__ __align__(16) __nv_bfloat16 g_w2l[(size_t)EE * HH * DD];
__device__ int   g_count[EE];
__device__ int   g_entry[EE * NTOK];          // packed: token*2 + slot
__device__ float g_wt[EE * NTOK];

__global__ void zero_counts_kernel() {
    if (threadIdx.x < EE) g_count[threadIdx.x] = 0;
}

// ---------------------------------------------------------------------------
// helpers
// ---------------------------------------------------------------------------
__device__ __forceinline__ uint32_t sm_u32(const void* p) {
    return (uint32_t)__cvta_generic_to_shared(p);
}
__device__ __forceinline__ void bsplit(float v, uint32_t& h, uint32_t& l) {
    __nv_bfloat16 bh = __float2bfloat16_rn(v);
    h = (uint32_t)__bfloat16_as_ushort(bh);
    l = (uint32_t)__bfloat16_as_ushort(__float2bfloat16_rn(v - __bfloat162float(bh)));
}

#define MMA_BF16(d, a0, a1, a2, a3, b0, b1)                                   \
    asm volatile(                                                             \
        "mma.sync.aligned.m16n8k16.row.col.f32.bf16.bf16.f32 "                \
        "{%0,%1,%2,%3}, {%4,%5,%6,%7}, {%8,%9}, {%0,%1,%2,%3};"               \
        : "+f"((d)[0]), "+f"((d)[1]), "+f"((d)[2]), "+f"((d)[3])              \
        : "r"(a0), "r"(a1), "r"(a2), "r"(a3), "r"(b0), "r"(b1))

#define LDSM_X4(r0, r1, r2, r3, addr)                                         \
    asm volatile("ldmatrix.sync.aligned.m8n8.x4.shared.b16 {%0,%1,%2,%3}, [%4];" \
        : "=r"(r0), "=r"(r1), "=r"(r2), "=r"(r3) : "r"(addr))

#define LDSM_X4T(r0, r1, r2, r3, addr)                                        \
    asm volatile("ldmatrix.sync.aligned.m8n8.x4.trans.shared.b16 {%0,%1,%2,%3}, [%4];" \
        : "=r"(r0), "=r"(r1), "=r"(r2), "=r"(r3) : "r"(addr))

// cp.async: A uses .ca (L1, co-resident CTAs share m-tile), B uses .cg (L2 only)
#define CPA(dst, src, sz)                                                     \
    asm volatile("cp.async.ca.shared.global [%0], [%1], 16, %2;"              \
        :: "r"(dst), "l"(src), "r"(sz) : "memory")
#define CPB(dst, src)                                                         \
    asm volatile("cp.async.cg.shared.global [%0], [%1], 16;"                  \
        :: "r"(dst), "l"(src) : "memory")
#define CP_COMMIT() asm volatile("cp.async.commit_group;" ::: "memory")
#define CP_WAIT0()  asm volatile("cp.async.wait_group 0;" ::: "memory")

// ---------------------------------------------------------------------------
// Pre-split: fp32 -> bf16 hi/lo pair, vectorized float4.
// ---------------------------------------------------------------------------
__global__ __launch_bounds__(256)
void presplit_kernel(const float* __restrict__ src,
                     __nv_bfloat16* __restrict__ h,
                     __nv_bfloat16* __restrict__ l, int n4)
{
    int i = blockIdx.x * 256 + threadIdx.x;
    if (i >= n4) return;
    float4 v = ((const float4*)src)[i];
    uint32_t hh[4], ll[4];
    bsplit(v.x, hh[0], ll[0]); bsplit(v.y, hh[1], ll[1]);
    bsplit(v.z, hh[2], ll[2]); bsplit(v.w, hh[3], ll[3]);
    ((uint2*)h)[i] = make_uint2(hh[0] | (hh[1] << 16), hh[2] | (hh[3] << 16));
    ((uint2*)l)[i] = make_uint2(ll[0] | (ll[1] << 16), ll[2] | (ll[3] << 16));
}

// ---------------------------------------------------------------------------
// Router: 32 tokens per block, weights staged in smem.
// ---------------------------------------------------------------------------
#define RTOK 32
#define RCH 116   // 928 / 8 chunks

__global__ __launch_bounds__(256)
void router_kernel(const float* __restrict__ x,
                   const float* __restrict__ dt,
                   const float* __restrict__ dd,
                   const float* __restrict__ dr,
                   const float* __restrict__ de,
                   const float* __restrict__ cemb,
                   const float* __restrict__ Wg,
                   const float* __restrict__ bg,
                   const float* __restrict__ Wn,
                   const float* __restrict__ bn,
                   const float* __restrict__ noise,
                   const int*   __restrict__ city,
                   float* __restrict__ gate1)
{
    __shared__ float Wsh[2 * EE][RCH];
    __shared__ float hsh[RTOK][RCH];
    __shared__ float lg[RTOK][2 * EE];

    const int tid = threadIdx.x;          // 256
    const int tb = blockIdx.x * RTOK;
    const int t = tid >> 3;               // token slot 0..31
    const int s = tid & 7;                // 0..7

    float acc0 = 0.f, acc1 = 0.f, acc2 = 0.f;

    for (int c = 0; c < 8; c++) {
        const int k0 = c * RCH;
        for (int i = tid; i < 2 * EE * RCH; i += 256) {
            int j = i / RCH, k = i % RCH;
            Wsh[j][k] = (j < EE) ? Wg[j * LIN + k0 + k] : Wn[(j - EE) * LIN + k0 + k];
        }
        for (int i = tid; i < RTOK * RCH; i += 256) {
            int tt = i / RCH, kk = i % RCH;
            int k = k0 + kk;
            int n = tb + tt;
            float v;
            if (k < DD)        v = x[n * DD + k];
            else if (k < 544)  v = cemb[city[n / TT] * CEC + (k - DD)];
            else if (k < 672)  v = dt[n * 128 + (k - 544)];
            else if (k < 800)  v = dd[n * 128 + (k - 672)];
            else if (k < 864)  v = dr[n * 64 + (k - 800)];
            else               v = de[n * 64 + (k - 864)];
            hsh[tt][kk] = v;
        }
        __syncthreads();
        for (int k = 0; k < RCH; k++) {
            float a = hsh[t][k];
            acc0 += a * Wsh[s][k];
            acc1 += a * Wsh[s + 8][k];
            if (s < 4) acc2 += a * Wsh[s + 16][k];
        }
        __syncthreads();
    }
    lg[t][s] = acc0;
    lg[t][s + 8] = acc1;
    if (s < 4) lg[t][s + 16] = acc2;
    __syncthreads();

    if (s == 0) {
        const int n = tb + t;
        float logits[EE], noisy[EE], ex[EE];
        float mx = -1e30f;
        for (int e = 0; e < EE; e++) { logits[e] = lg[t][e] + bg[e]; mx = fmaxf(mx, logits[e]); }
        float ssum = 0.f;
        for (int e = 0; e < EE; e++) { ex[e] = expf(logits[e] - mx); ssum += ex[e]; }
        const float rinv = 1.f / ssum;
        for (int e = 0; e < EE; e++) gate1[n * EE + e] = ex[e] * rinv;

        for (int e = 0; e < EE; e++) {
            const float z  = lg[t][EE + e] + bn[e];
            const float sp = fmaxf(z, 0.f) + log1pf(expf(-fabsf(z)));  // stable softplus
            noisy[e] = logits[e] + noise[n * EE + e] * sp;
        }
        int i0 = 0;
        for (int e = 1; e < EE; e++) if (noisy[e] > noisy[i0]) i0 = e;
        int i1 = (i0 == 0) ? 1 : 0;
        for (int e = 0; e < EE; e++) if (e != i0 && noisy[e] > noisy[i1]) i1 = e;

        const float m  = fmaxf(noisy[i0], noisy[i1]);
        const float s0 = expf(noisy[i0] - m), s1 = expf(noisy[i1] - m);
        const float inv = 1.f / (s0 + s1);

        int p0 = atomicAdd(&g_count[i0], 1);
        g_entry[i0 * NTOK + p0] = 2 * n;
        g_wt[i0 * NTOK + p0]    = s0 * inv;
        int p1 = atomicAdd(&g_count[i1], 1);
        g_entry[i1 * NTOK + p1] = 2 * n + 1;
        g_wt[i1 * NTOK + p1]    = s1 * inv;
    }
}

// ---------------------------------------------------------------------------
// Gathered expert GEMM: mma.sync m16n8k16 bf16, 3xBF16 split, fp32 accum.
// All operands pre-split to bf16 hi/lo in gmem; fills are pure cp.async.
//   IS_FFN2 == false: hid(hi,lo)[pair] = split(gelu(x[tok] @ W1[e] + b1[e]))
//   IS_FFN2 == true : out[tok] += w * (hid[pair] @ W2[e] + b2[e])
// Block 128x128, BK=32 (2 k-steps of 16), 8 warps 4x2, warp tile 32x64.
// 2 CTAs/SM; pipeline: wait -> sync -> cp.async fill(next) -> compute(cur).
// ---------------------------------------------------------------------------
template<int KTOT, int LDW, bool IS_FFN2>
__global__ __launch_bounds__(256, 2)
void moe_mma_kernel(const float* __restrict__ bias,
                    float* __restrict__ outp)
{
    constexpr int NT = KTOT / BK;
    const int e  = blockIdx.z;
    const int m0 = blockIdx.y * BM;
    const int n0 = blockIdx.x * BN;
    const int L  = g_count[e];
    if (m0 >= L) return;

    extern __shared__ char smem[];
    __shared__ int   toks[BM];
    __shared__ float wts[BM];

    const int tid  = threadIdx.x;
    const int wid  = tid >> 5;
    const int lane = tid & 31;

    if (tid < BM) {
        int i = m0 + tid;
        toks[tid] = (i < L) ? g_entry[e * NTOK + i] : -1;
        wts[tid]  = (IS_FFN2 && i < L) ? g_wt[e * NTOK + i] : 0.f;
    }
    __syncthreads();

    const char* Ah = IS_FFN2 ? (const char*)g_hid_h : (const char*)g_xh;
    const char* Al = IS_FFN2 ? (const char*)g_hid_l : (const char*)g_xl;
    const char* Wh = IS_FFN2 ? (const char*)g_w2h : (const char*)g_w1h;
    const char* Wl = IS_FFN2 ? (const char*)g_w2l : (const char*)g_w1l;

    // ---- cp.async fills ----
    auto fill_stage = [&](int buf, int k0) {
        char* st = smem + buf * STAGE;
        // A: 128 rows x 4 chunks of 16B, hi+lo; 2 passes
        #pragma unroll
        for (int p = 0; p < 2; p++) {
            const int idx = p * 256 + tid;
            const int r = idx >> 2, c = idx & 3;
            const int ent = toks[r];
            const int row = ent >= 0 ? (IS_FFN2 ? ent : (ent >> 1)) : 0;
            const uint32_t sz = ent >= 0 ? 16u : 0u;
            const size_t so = ((size_t)row * KTOT + k0 + c * 8) * 2;
            CPA(sm_u32(st + OFF_AH + r * 80 + c * 16), Ah + so, sz);
            CPA(sm_u32(st + OFF_AL + r * 80 + c * 16), Al + so, sz);
        }
        // B: 32 k-rows x 16 chunks of 16B, hi+lo; 2 passes
        const size_t wbase = ((size_t)e * KTOT + k0) * LDW + n0;
        #pragma unroll
        for (int p = 0; p < 2; p++) {
            const int idx = p * 256 + tid;
            const int k = idx >> 4, c = idx & 15;
            const size_t so = (wbase + (size_t)k * LDW + c * 8) * 2;
            const int doff = k * 256 + ((c ^ (k & 7)) * 16);
            CPB(sm_u32(st + OFF_BH + doff), Wh + so);
            CPB(sm_u32(st + OFF_BL + doff), Wl + so);
        }
    };

    // ---- accumulators ----
    const int wm = wid >> 1, wn = wid & 1;
    float acc[2][8][4];
    #pragma unroll
    for (int mt = 0; mt < 2; mt++)
        #pragma unroll
        for (int nn = 0; nn < 8; nn++)
            #pragma unroll
            for (int i = 0; i < 4; i++) acc[mt][nn][i] = 0.f;

    auto compute_stage = [&](int buf) {
        char* st = smem + buf * STAGE;
        const uint32_t ah = sm_u32(st + OFF_AH);
        const uint32_t al = sm_u32(st + OFF_AL);
        const uint32_t bh = sm_u32(st + OFF_BH);
        const uint32_t bl = sm_u32(st + OFF_BL);
        #pragma unroll
        for (int ks = 0; ks < 2; ks++) {
            // A frags: rows lane&15, k-half lane>>4
            uint32_t a_h[2][4], a_l[2][4];
            #pragma unroll
            for (int mt = 0; mt < 2; mt++) {
                const uint32_t ao = (wm * 32 + mt * 16 + (lane & 15)) * 80
                                  + ks * 32 + (lane >> 4) * 16;
                LDSM_X4(a_h[mt][0], a_h[mt][1], a_h[mt][2], a_h[mt][3], ah + ao);
                LDSM_X4(a_l[mt][0], a_l[mt][1], a_l[mt][2], a_l[mt][3], al + ao);
            }
            // B frags loaded per-bt to cap live registers
            #pragma unroll
            for (int bt = 0; bt < 4; bt++) {
                uint32_t bfh[4], bfl[4];
                const int k = ks * 16 + (lane & 15);
                const int c = ((wn * 64 + bt * 16) >> 3) + (lane >> 4);
                const uint32_t bo = k * 256 + ((c ^ (lane & 7)) * 16);
                LDSM_X4T(bfh[0], bfh[1], bfh[2], bfh[3], bh + bo);
                LDSM_X4T(bfl[0], bfl[1], bfl[2], bfl[3], bl + bo);
                #pragma unroll
                for (int mt = 0; mt < 2; mt++) {
                    float* d0 = acc[mt][2 * bt];
                    float* d1 = acc[mt][2 * bt + 1];
                    MMA_BF16(d0, a_h[mt][0], a_h[mt][1], a_h[mt][2], a_h[mt][3],
                             bfh[0], bfh[1]);
                    MMA_BF16(d0, a_h[mt][0], a_h[mt][1], a_h[mt][2], a_h[mt][3],
                             bfl[0], bfl[1]);
                    MMA_BF16(d0, a_l[mt][0], a_l[mt][1], a_l[mt][2], a_l[mt][3],
                             bfh[0], bfh[1]);
                    MMA_BF16(d1, a_h[mt][0], a_h[mt][1], a_h[mt][2], a_h[mt][3],
                             bfh[2], bfh[3]);
                    MMA_BF16(d1, a_h[mt][0], a_h[mt][1], a_h[mt][2], a_h[mt][3],
                             bfl[2], bfl[3]);
                    MMA_BF16(d1, a_l[mt][0], a_l[mt][1], a_l[mt][2], a_l[mt][3],
                             bfh[2], bfh[3]);
                }
            }
        }
    };

    // ---- mainloop: wait(cur) -> sync -> fill(next, async) -> compute(cur) ----
    fill_stage(0, 0);
    CP_COMMIT();
    for (int t = 0; t < NT; t++) {
        CP_WAIT0();
        __syncthreads();
        if (t + 1 < NT) {
            fill_stage((t + 1) & 1, (t + 1) * BK);
            CP_COMMIT();
        }
        compute_stage(t & 1);
    }

    // ---- epilogue ----
    const int g  = lane >> 2;
    const int kq = lane & 3;
    const float* be = bias + e * LDW;
    #pragma unroll
    for (int mt = 0; mt < 2; mt++) {
        const int lr0  = wm * 32 + mt * 16 + g;
        const int ent0 = toks[lr0];
        const int ent1 = toks[lr0 + 8];
        #pragma unroll
        for (int nn = 0; nn < 8; nn++) {
            const int c = n0 + wn * 64 + nn * 8 + 2 * kq;
            const float bb0 = be[c], bb1 = be[c + 1];
            if (!IS_FFN2) {
                if (ent0 >= 0) {
                    float v0 = acc[mt][nn][0] + bb0;
                    float v1 = acc[mt][nn][1] + bb1;
                    v0 = 0.5f * v0 * (1.f + erff(v0 * 0.70710678118654752f));
                    v1 = 0.5f * v1 * (1.f + erff(v1 * 0.70710678118654752f));
                    uint32_t h0, l0, h1, l1;
                    bsplit(v0, h0, l0); bsplit(v1, h1, l1);
                    const size_t o = ((size_t)ent0 * HH + c) * 2;
                    *(uint32_t*)((char*)g_hid_h + o) = h0 | (h1 << 16);
                    *(uint32_t*)((char*)g_hid_l + o) = l0 | (l1 << 16);
                }
                if (ent1 >= 0) {
                    float v0 = acc[mt][nn][2] + bb0;
                    float v1 = acc[mt][nn][3] + bb1;
                    v0 = 0.5f * v0 * (1.f + erff(v0 * 0.70710678118654752f));
                    v1 = 0.5f * v1 * (1.f + erff(v1 * 0.70710678118654752f));
                    uint32_t h0, l0, h1, l1;
                    bsplit(v0, h0, l0); bsplit(v1, h1, l1);
                    const size_t o = ((size_t)ent1 * HH + c) * 2;
                    *(uint32_t*)((char*)g_hid_h + o) = h0 | (h1 << 16);
                    *(uint32_t*)((char*)g_hid_l + o) = l0 | (l1 << 16);
                }
            } else {
                if (ent0 >= 0) {
                    const float w = wts[lr0];
                    float* o = outp + (size_t)(ent0 >> 1) * DD + c;
                    atomicAdd(o,     w * (acc[mt][nn][0] + bb0));
                    atomicAdd(o + 1, w * (acc[mt][nn][1] + bb1));
                }
                if (ent1 >= 0) {
                    const float w = wts[lr0 + 8];
                    float* o = outp + (size_t)(ent1 >> 1) * DD + c;
                    atomicAdd(o,     w * (acc[mt][nn][2] + bb0));
                    atomicAdd(o + 1, w * (acc[mt][nn][3] + bb1));
                }
            }
        }
    }
}

// ---------------------------------------------------------------------------
extern "C" void kernel_launch(void* const* d_in, const int* in_sizes, int n_in,
                              void* d_out, int out_size)
{
    const float* x    = (const float*)d_in[0];
    const float* dt   = (const float*)d_in[1];
    const float* dd   = (const float*)d_in[2];
    const float* dr   = (const float*)d_in[3];
    const float* de   = (const float*)d_in[4];
    const float* cemb = (const float*)d_in[5];
    const float* Wg   = (const float*)d_in[6];
    const float* bg   = (const float*)d_in[7];
    const float* Wn   = (const float*)d_in[8];
    const float* bn   = (const float*)d_in[9];
    const float* W1   = (const float*)d_in[10];
    const float* b1   = (const float*)d_in[11];
    const float* W2   = (const float*)d_in[12];
    const float* b2   = (const float*)d_in[13];
    const float* noise= (const float*)d_in[14];
    const int*   city = (const int*)d_in[15];

    float* out   = (float*)d_out;                       // (4096, 512)
    float* gate1 = (float*)d_out + (size_t)NTOK * DD;   // (4096, 10)

    cudaFuncSetAttribute((const void*)moe_mma_kernel<DD, HH, false>,
                         cudaFuncAttributeMaxDynamicSharedMemorySize, SMEM_DYN);
    cudaFuncSetAttribute((const void*)moe_mma_kernel<HH, DD, true>,
                         cudaFuncAttributeMaxDynamicSharedMemorySize, SMEM_DYN);

    cudaMemsetAsync(d_out, 0, (size_t)NTOK * DD * sizeof(float));
    zero_counts_kernel<<<1, 32>>>();

    // pre-split operands to bf16 hi/lo (once)
    {
        __nv_bfloat16 *xh, *xl, *w1h, *w1l, *w2h, *w2l;
        cudaGetSymbolAddress((void**)&xh,  g_xh);
        cudaGetSymbolAddress((void**)&xl,  g_xl);
        cudaGetSymbolAddress((void**)&w1h, g_w1h);
        cudaGetSymbolAddress((void**)&w1l, g_w1l);
        cudaGetSymbolAddress((void**)&w2h, g_w2h);
        cudaGetSymbolAddress((void**)&w2l, g_w2l);
        const int nx = NTOK * DD / 4;
        const int nw = EE * DD * HH / 4;
        presplit_kernel<<<(nx + 255) / 256, 256>>>(x,  xh,  xl,  nx);
        presplit_kernel<<<(nw + 255) / 256, 256>>>(W1, w1h, w1l, nw);
        presplit_kernel<<<(nw + 255) / 256, 256>>>(W2, w2h, w2l, nw);
    }

    router_kernel<<<NTOK / RTOK, 256>>>(x, dt, dd, dr, de, cemb, Wg, bg, Wn, bn,
                                        noise, city, gate1);

    dim3 grid1(HH / BN, NTOK / BM, EE);   // (16, 32, 10)
    moe_mma_kernel<DD, HH, false><<<grid1, 256, SMEM_DYN>>>(b1, nullptr);

    dim3 grid2(DD / BN, NTOK / BM, EE);   // (4, 32, 10)
    moe_mma_kernel<HH, DD, true><<<grid2, 256, SMEM_DYN>>>(b2, out);
}

// round 10
// speedup vs baseline: 4.6057x; 1.0088x over previous
#include <cuda_runtime.h>
#include <cuda_bf16.h>
#include <math.h>
#include <stdint.h>

#define TT 1024
#define DD 512
#define EE 10
#define HH 2048
#define CEC 32
#define LIN 928
#define NTOK 4096
#define NPAIR 8192

#define BM 128
#define BN 128
#define BK 32           // bf16 k per stage

// A tile: 128 rows x 32 bf16, 80B pitch (conflict-free ldmatrix) = 10240B
// B tile: 32 k-rows x 128 bf16, 256B pitch, chunk-XOR swizzle = 8192B
#define A_TILE 10240
#define B_TILE 8192
#define OFF_AH 0
#define OFF_AL A_TILE
#define OFF_BH (2 * A_TILE)
#define OFF_BL (2 * A_TILE + B_TILE)
#define STAGE  (2 * A_TILE + 2 * B_TILE)   // 36864
#define SMEM_DYN (2 * STAGE)               // 73728

// Scratch (static device arrays — no allocation allowed)
__device__ __align__(16) __nv_bfloat16 g_hid_h[(size_t)NPAIR * HH];   // 32 MB
__device__ __align__(16) __nv_bfloat16 g_hid_l[(size_t)NPAIR * HH];   // 32 MB
__device__ __align__(16) __nv_bfloat16 g_xh[(size_t)NTOK * DD];
__device__ __align__(16) __nv_bfloat16 g_xl[(size_t)NTOK * DD];
__device__ __align__(16) __nv_bfloat16 g_w1h[(size_t)EE * DD * HH];
__device__ __align__(16) __nv_bfloat16 g_w1l[(size_t)EE * DD * HH];
__device__ __align__(16) __nv_bfloat16 g_w2h[(size_t)EE * HH * DD];
__device__ __align__(16) __nv_bfloat16 g_w2l[(size_t)EE * HH * DD];
__device__ int   g_count[EE];
__device__ int   g_entry[EE * NTOK];          // packed: token*2 + slot
__device__ float g_wt[EE * NTOK];

__global__ void zero_counts_kernel() {
    if (threadIdx.x < EE) g_count[threadIdx.x] = 0;
}

// ---------------------------------------------------------------------------
// helpers
// ---------------------------------------------------------------------------
__device__ __forceinline__ uint32_t sm_u32(const void* p) {
    return (uint32_t)__cvta_generic_to_shared(p);
}
__device__ __forceinline__ void bsplit(float v, uint32_t& h, uint32_t& l) {
    __nv_bfloat16 bh = __float2bfloat16_rn(v);
    h = (uint32_t)__bfloat16_as_ushort(bh);
    l = (uint32_t)__bfloat16_as_ushort(__float2bfloat16_rn(v - __bfloat162float(bh)));
}

#define MMA_BF16(d, a0, a1, a2, a3, b0, b1)                                   \
    asm volatile(                                                             \
        "mma.sync.aligned.m16n8k16.row.col.f32.bf16.bf16.f32 "                \
        "{%0,%1,%2,%3}, {%4,%5,%6,%7}, {%8,%9}, {%0,%1,%2,%3};"               \
        : "+f"((d)[0]), "+f"((d)[1]), "+f"((d)[2]), "+f"((d)[3])              \
        : "r"(a0), "r"(a1), "r"(a2), "r"(a3), "r"(b0), "r"(b1))

#define LDSM_X4(r0, r1, r2, r3, addr)                                         \
    asm volatile("ldmatrix.sync.aligned.m8n8.x4.shared.b16 {%0,%1,%2,%3}, [%4];" \
        : "=r"(r0), "=r"(r1), "=r"(r2), "=r"(r3) : "r"(addr))

#define LDSM_X4T(r0, r1, r2, r3, addr)                                        \
    asm volatile("ldmatrix.sync.aligned.m8n8.x4.trans.shared.b16 {%0,%1,%2,%3}, [%4];" \
        : "=r"(r0), "=r"(r1), "=r"(r2), "=r"(r3) : "r"(addr))

// cp.async: A uses .ca (L1, co-resident CTAs share m-tile), B uses .cg (L2 only)
#define CPA(dst, src, sz)                                                     \
    asm volatile("cp.async.ca.shared.global [%0], [%1], 16, %2;"              \
        :: "r"(dst), "l"(src), "r"(sz) : "memory")
#define CPB(dst, src)                                                         \
    asm volatile("cp.async.cg.shared.global [%0], [%1], 16;"                  \
        :: "r"(dst), "l"(src) : "memory")
#define CP_COMMIT() asm volatile("cp.async.commit_group;" ::: "memory")
#define CP_WAIT0()  asm volatile("cp.async.wait_group 0;" ::: "memory")

// ---------------------------------------------------------------------------
// Pre-split: fp32 -> bf16 hi/lo pair, vectorized float4.
// ---------------------------------------------------------------------------
__global__ __launch_bounds__(256)
void presplit_kernel(const float* __restrict__ src,
                     __nv_bfloat16* __restrict__ h,
                     __nv_bfloat16* __restrict__ l, int n4)
{
    int i = blockIdx.x * 256 + threadIdx.x;
    if (i >= n4) return;
    float4 v = ((const float4*)src)[i];
    uint32_t hh[4], ll[4];
    bsplit(v.x, hh[0], ll[0]); bsplit(v.y, hh[1], ll[1]);
    bsplit(v.z, hh[2], ll[2]); bsplit(v.w, hh[3], ll[3]);
    ((uint2*)h)[i] = make_uint2(hh[0] | (hh[1] << 16), hh[2] | (hh[3] << 16));
    ((uint2*)l)[i] = make_uint2(ll[0] | (ll[1] << 16), ll[2] | (ll[3] << 16));
}

// ---------------------------------------------------------------------------
// Router: 32 tokens per block, weights staged in smem.
// ---------------------------------------------------------------------------
#define RTOK 32
#define RCH 116   // 928 / 8 chunks

__global__ __launch_bounds__(256)
void router_kernel(const float* __restrict__ x,
                   const float* __restrict__ dt,
                   const float* __restrict__ dd,
                   const float* __restrict__ dr,
                   const float* __restrict__ de,
                   const float* __restrict__ cemb,
                   const float* __restrict__ Wg,
                   const float* __restrict__ bg,
                   const float* __restrict__ Wn,
                   const float* __restrict__ bn,
                   const float* __restrict__ noise,
                   const int*   __restrict__ city,
                   float* __restrict__ gate1)
{
    __shared__ float Wsh[2 * EE][RCH];
    __shared__ float hsh[RTOK][RCH];
    __shared__ float lg[RTOK][2 * EE];

    const int tid = threadIdx.x;          // 256
    const int tb = blockIdx.x * RTOK;
    const int t = tid >> 3;               // token slot 0..31
    const int s = tid & 7;                // 0..7

    float acc0 = 0.f, acc1 = 0.f, acc2 = 0.f;

    for (int c = 0; c < 8; c++) {
        const int k0 = c * RCH;
        for (int i = tid; i < 2 * EE * RCH; i += 256) {
            int j = i / RCH, k = i % RCH;
            Wsh[j][k] = (j < EE) ? Wg[j * LIN + k0 + k] : Wn[(j - EE) * LIN + k0 + k];
        }
        for (int i = tid; i < RTOK * RCH; i += 256) {
            int tt = i / RCH, kk = i % RCH;
            int k = k0 + kk;
            int n = tb + tt;
            float v;
            if (k < DD)        v = x[n * DD + k];
            else if (k < 544)  v = cemb[city[n / TT] * CEC + (k - DD)];
            else if (k < 672)  v = dt[n * 128 + (k - 544)];
            else if (k < 800)  v = dd[n * 128 + (k - 672)];
            else if (k < 864)  v = dr[n * 64 + (k - 800)];
            else               v = de[n * 64 + (k - 864)];
            hsh[tt][kk] = v;
        }
        __syncthreads();
        for (int k = 0; k < RCH; k++) {
            float a = hsh[t][k];
            acc0 += a * Wsh[s][k];
            acc1 += a * Wsh[s + 8][k];
            if (s < 4) acc2 += a * Wsh[s + 16][k];
        }
        __syncthreads();
    }
    lg[t][s] = acc0;
    lg[t][s + 8] = acc1;
    if (s < 4) lg[t][s + 16] = acc2;
    __syncthreads();

    if (s == 0) {
        const int n = tb + t;
        float logits[EE], noisy[EE], ex[EE];
        float mx = -1e30f;
        for (int e = 0; e < EE; e++) { logits[e] = lg[t][e] + bg[e]; mx = fmaxf(mx, logits[e]); }
        float ssum = 0.f;
        for (int e = 0; e < EE; e++) { ex[e] = expf(logits[e] - mx); ssum += ex[e]; }
        const float rinv = 1.f / ssum;
        for (int e = 0; e < EE; e++) gate1[n * EE + e] = ex[e] * rinv;

        for (int e = 0; e < EE; e++) {
            const float z  = lg[t][EE + e] + bn[e];
            const float sp = fmaxf(z, 0.f) + log1pf(expf(-fabsf(z)));  // stable softplus
            noisy[e] = logits[e] + noise[n * EE + e] * sp;
        }
        int i0 = 0;
        for (int e = 1; e < EE; e++) if (noisy[e] > noisy[i0]) i0 = e;
        int i1 = (i0 == 0) ? 1 : 0;
        for (int e = 0; e < EE; e++) if (e != i0 && noisy[e] > noisy[i1]) i1 = e;

        const float m  = fmaxf(noisy[i0], noisy[i1]);
        const float s0 = expf(noisy[i0] - m), s1 = expf(noisy[i1] - m);
        const float inv = 1.f / (s0 + s1);

        int p0 = atomicAdd(&g_count[i0], 1);
        g_entry[i0 * NTOK + p0] = 2 * n;
        g_wt[i0 * NTOK + p0]    = s0 * inv;
        int p1 = atomicAdd(&g_count[i1], 1);
        g_entry[i1 * NTOK + p1] = 2 * n + 1;
        g_wt[i1 * NTOK + p1]    = s1 * inv;
    }
}

// ---------------------------------------------------------------------------
// Gathered expert GEMM: mma.sync m16n8k16 bf16, 3xBF16 split, fp32 accum.
// All operands pre-split to bf16 hi/lo in gmem; fills are pure cp.async.
//   IS_FFN2 == false: hid(hi,lo)[pair] = split(gelu(x[tok] @ W1[e] + b1[e]))
//   IS_FFN2 == true : out[tok] += w * (hid[pair] @ W2[e] + b2[e])
// Block 128x128, BK=32 (2 k-steps of 16), 8 warps 4x2, warp tile 32x64.
// 2 CTAs/SM; pipeline: wait -> sync -> cp.async fill(next) -> compute(cur).
// ---------------------------------------------------------------------------
template<int KTOT, int LDW, bool IS_FFN2>
__global__ __launch_bounds__(256, 2)
void moe_mma_kernel(const float* __restrict__ bias,
                    float* __restrict__ outp)
{
    constexpr int NT = KTOT / BK;
    const int e  = blockIdx.z;
    const int m0 = blockIdx.y * BM;
    const int n0 = blockIdx.x * BN;
    const int L  = g_count[e];
    if (m0 >= L) return;

    extern __shared__ char smem[];
    __shared__ int   toks[BM];
    __shared__ float wts[BM];

    const int tid  = threadIdx.x;
    const int wid  = tid >> 5;
    const int lane = tid & 31;

    if (tid < BM) {
        int i = m0 + tid;
        toks[tid] = (i < L) ? g_entry[e * NTOK + i] : -1;
        wts[tid]  = (IS_FFN2 && i < L) ? g_wt[e * NTOK + i] : 0.f;
    }
    __syncthreads();

    const char* Ah = IS_FFN2 ? (const char*)g_hid_h : (const char*)g_xh;
    const char* Al = IS_FFN2 ? (const char*)g_hid_l : (const char*)g_xl;
    const char* Wh = IS_FFN2 ? (const char*)g_w2h : (const char*)g_w1h;
    const char* Wl = IS_FFN2 ? (const char*)g_w2l : (const char*)g_w1l;

    // ---- cp.async fills ----
    auto fill_stage = [&](int buf, int k0) {
        char* st = smem + buf * STAGE;
        // A: 128 rows x 4 chunks of 16B, hi+lo; 2 passes
        #pragma unroll
        for (int p = 0; p < 2; p++) {
            const int idx = p * 256 + tid;
            const int r = idx >> 2, c = idx & 3;
            const int ent = toks[r];
            const int row = ent >= 0 ? (IS_FFN2 ? ent : (ent >> 1)) : 0;
            const uint32_t sz = ent >= 0 ? 16u : 0u;
            const size_t so = ((size_t)row * KTOT + k0 + c * 8) * 2;
            CPA(sm_u32(st + OFF_AH + r * 80 + c * 16), Ah + so, sz);
            CPA(sm_u32(st + OFF_AL + r * 80 + c * 16), Al + so, sz);
        }
        // B: 32 k-rows x 16 chunks of 16B, hi+lo; 2 passes
        const size_t wbase = ((size_t)e * KTOT + k0) * LDW + n0;
        #pragma unroll
        for (int p = 0; p < 2; p++) {
            const int idx = p * 256 + tid;
            const int k = idx >> 4, c = idx & 15;
            const size_t so = (wbase + (size_t)k * LDW + c * 8) * 2;
            const int doff = k * 256 + ((c ^ (k & 7)) * 16);
            CPB(sm_u32(st + OFF_BH + doff), Wh + so);
            CPB(sm_u32(st + OFF_BL + doff), Wl + so);
        }
    };

    // ---- accumulators ----
    const int wm = wid >> 1, wn = wid & 1;
    float acc[2][8][4];
    #pragma unroll
    for (int mt = 0; mt < 2; mt++)
        #pragma unroll
        for (int nn = 0; nn < 8; nn++)
            #pragma unroll
            for (int i = 0; i < 4; i++) acc[mt][nn][i] = 0.f;

    auto compute_stage = [&](int buf) {
        char* st = smem + buf * STAGE;
        const uint32_t ah = sm_u32(st + OFF_AH);
        const uint32_t al = sm_u32(st + OFF_AL);
        const uint32_t bh = sm_u32(st + OFF_BH);
        const uint32_t bl = sm_u32(st + OFF_BL);
        #pragma unroll
        for (int ks = 0; ks < 2; ks++) {
            // A frags: rows lane&15, k-half lane>>4
            uint32_t a_h[2][4], a_l[2][4];
            #pragma unroll
            for (int mt = 0; mt < 2; mt++) {
                const uint32_t ao = (wm * 32 + mt * 16 + (lane & 15)) * 80
                                  + ks * 32 + (lane >> 4) * 16;
                LDSM_X4(a_h[mt][0], a_h[mt][1], a_h[mt][2], a_h[mt][3], ah + ao);
                LDSM_X4(a_l[mt][0], a_l[mt][1], a_l[mt][2], a_l[mt][3], al + ao);
            }
            // B frags loaded per-bt to cap live registers
            #pragma unroll
            for (int bt = 0; bt < 4; bt++) {
                uint32_t bfh[4], bfl[4];
                const int k = ks * 16 + (lane & 15);
                const int c = ((wn * 64 + bt * 16) >> 3) + (lane >> 4);
                const uint32_t bo = k * 256 + ((c ^ (lane & 7)) * 16);
                LDSM_X4T(bfh[0], bfh[1], bfh[2], bfh[3], bh + bo);
                LDSM_X4T(bfl[0], bfl[1], bfl[2], bfl[3], bl + bo);
                #pragma unroll
                for (int mt = 0; mt < 2; mt++) {
                    float* d0 = acc[mt][2 * bt];
                    float* d1 = acc[mt][2 * bt + 1];
                    MMA_BF16(d0, a_h[mt][0], a_h[mt][1], a_h[mt][2], a_h[mt][3],
                             bfh[0], bfh[1]);
                    MMA_BF16(d0, a_h[mt][0], a_h[mt][1], a_h[mt][2], a_h[mt][3],
                             bfl[0], bfl[1]);
                    MMA_BF16(d0, a_l[mt][0], a_l[mt][1], a_l[mt][2], a_l[mt][3],
                             bfh[0], bfh[1]);
                    MMA_BF16(d1, a_h[mt][0], a_h[mt][1], a_h[mt][2], a_h[mt][3],
                             bfh[2], bfh[3]);
                    MMA_BF16(d1, a_h[mt][0], a_h[mt][1], a_h[mt][2], a_h[mt][3],
                             bfl[2], bfl[3]);
                    MMA_BF16(d1, a_l[mt][0], a_l[mt][1], a_l[mt][2], a_l[mt][3],
                             bfh[2], bfh[3]);
                }
            }
        }
    };

    // ---- mainloop: wait(cur) -> sync -> fill(next, async) -> compute(cur) ----
    fill_stage(0, 0);
    CP_COMMIT();
    for (int t = 0; t < NT; t++) {
        CP_WAIT0();
        __syncthreads();
        if (t + 1 < NT) {
            fill_stage((t + 1) & 1, (t + 1) * BK);
            CP_COMMIT();
        }
        compute_stage(t & 1);
    }

    // ---- epilogue ----
    const int g  = lane >> 2;
    const int kq = lane & 3;
    const float* be = bias + e * LDW;
    #pragma unroll
    for (int mt = 0; mt < 2; mt++) {
        const int lr0  = wm * 32 + mt * 16 + g;
        const int ent0 = toks[lr0];
        const int ent1 = toks[lr0 + 8];
        #pragma unroll
        for (int nn = 0; nn < 8; nn++) {
            const int c = n0 + wn * 64 + nn * 8 + 2 * kq;
            const float bb0 = be[c], bb1 = be[c + 1];
            if (!IS_FFN2) {
                if (ent0 >= 0) {
                    float v0 = acc[mt][nn][0] + bb0;
                    float v1 = acc[mt][nn][1] + bb1;
                    v0 = 0.5f * v0 * (1.f + erff(v0 * 0.70710678118654752f));
                    v1 = 0.5f * v1 * (1.f + erff(v1 * 0.70710678118654752f));
                    uint32_t h0, l0, h1, l1;
                    bsplit(v0, h0, l0); bsplit(v1, h1, l1);
                    const size_t o = ((size_t)ent0 * HH + c) * 2;
                    *(uint32_t*)((char*)g_hid_h + o) = h0 | (h1 << 16);
                    *(uint32_t*)((char*)g_hid_l + o) = l0 | (l1 << 16);
                }
                if (ent1 >= 0) {
                    float v0 = acc[mt][nn][2] + bb0;
                    float v1 = acc[mt][nn][3] + bb1;
                    v0 = 0.5f * v0 * (1.f + erff(v0 * 0.70710678118654752f));
                    v1 = 0.5f * v1 * (1.f + erff(v1 * 0.70710678118654752f));
                    uint32_t h0, l0, h1, l1;
                    bsplit(v0, h0, l0); bsplit(v1, h1, l1);
                    const size_t o = ((size_t)ent1 * HH + c) * 2;
                    *(uint32_t*)((char*)g_hid_h + o) = h0 | (h1 << 16);
                    *(uint32_t*)((char*)g_hid_l + o) = l0 | (l1 << 16);
                }
            } else {
                if (ent0 >= 0) {
                    const float w = wts[lr0];
                    float* o = outp + (size_t)(ent0 >> 1) * DD + c;
                    atomicAdd(o,     w * (acc[mt][nn][0] + bb0));
                    atomicAdd(o + 1, w * (acc[mt][nn][1] + bb1));
                }
                if (ent1 >= 0) {
                    const float w = wts[lr0 + 8];
                    float* o = outp + (size_t)(ent1 >> 1) * DD + c;
                    atomicAdd(o,     w * (acc[mt][nn][2] + bb0));
                    atomicAdd(o + 1, w * (acc[mt][nn][3] + bb1));
                }
            }
        }
    }
}

// ---------------------------------------------------------------------------
extern "C" void kernel_launch(void* const* d_in, const int* in_sizes, int n_in,
                              void* d_out, int out_size)
{
    const float* x    = (const float*)d_in[0];
    const float* dt   = (const float*)d_in[1];
    const float* dd   = (const float*)d_in[2];
    const float* dr   = (const float*)d_in[3];
    const float* de   = (const float*)d_in[4];
    const float* cemb = (const float*)d_in[5];
    const float* Wg   = (const float*)d_in[6];
    const float* bg   = (const float*)d_in[7];
    const float* Wn   = (const float*)d_in[8];
    const float* bn   = (const float*)d_in[9];
    const float* W1   = (const float*)d_in[10];
    const float* b1   = (const float*)d_in[11];
    const float* W2   = (const float*)d_in[12];
    const float* b2   = (const float*)d_in[13];
    const float* noise= (const float*)d_in[14];
    const int*   city = (const int*)d_in[15];

    float* out   = (float*)d_out;                       // (4096, 512)
    float* gate1 = (float*)d_out + (size_t)NTOK * DD;   // (4096, 10)

    cudaFuncSetAttribute((const void*)moe_mma_kernel<DD, HH, false>,
                         cudaFuncAttributeMaxDynamicSharedMemorySize, SMEM_DYN);
    cudaFuncSetAttribute((const void*)moe_mma_kernel<HH, DD, true>,
                         cudaFuncAttributeMaxDynamicSharedMemorySize, SMEM_DYN);

    cudaMemsetAsync(d_out, 0, (size_t)NTOK * DD * sizeof(float));
    zero_counts_kernel<<<1, 32>>>();

    // pre-split operands to bf16 hi/lo (once)
    {
        __nv_bfloat16 *xh, *xl, *w1h, *w1l, *w2h, *w2l;
        cudaGetSymbolAddress((void**)&xh,  g_xh);
        cudaGetSymbolAddress((void**)&xl,  g_xl);
        cudaGetSymbolAddress((void**)&w1h, g_w1h);
        cudaGetSymbolAddress((void**)&w1l, g_w1l);
        cudaGetSymbolAddress((void**)&w2h, g_w2h);
        cudaGetSymbolAddress((void**)&w2l, g_w2l);
        const int nx = NTOK * DD / 4;
        const int nw = EE * DD * HH / 4;
        presplit_kernel<<<(nx + 255) / 256, 256>>>(x,  xh,  xl,  nx);
        presplit_kernel<<<(nw + 255) / 256, 256>>>(W1, w1h, w1l, nw);
        presplit_kernel<<<(nw + 255) / 256, 256>>>(W2, w2h, w2l, nw);
    }

    router_kernel<<<NTOK / RTOK, 256>>>(x, dt, dd, dr, de, cemb, Wg, bg, Wn, bn,
                                        noise, city, gate1);

    dim3 grid1(HH / BN, NTOK / BM, EE);   // (16, 32, 10)
    moe_mma_kernel<DD, HH, false><<<grid1, 256, SMEM_DYN>>>(b1, nullptr);

    dim3 grid2(DD / BN, NTOK / BM, EE);   // (4, 32, 10)
    moe_mma_kernel<HH, DD, true><<<grid2, 256, SMEM_DYN>>>(b2, out);
}